// round 1
// baseline (speedup 1.0000x reference)
#include <cuda_runtime.h>
#include <math.h>

#define B_ 4
#define N_ 2048
#define E_ 1024
#define H_ 16
#define D_ 64
#define M_ (B_*N_)   // 8192

// Scratch: Q,K,V,attn-out in [b,h,n,d] layout. 4 x 32MB.
__device__ float g_Q[(size_t)B_*H_*N_*D_];
__device__ float g_K[(size_t)B_*H_*N_*D_];
__device__ float g_V[(size_t)B_*H_*N_*D_];
__device__ float g_A[(size_t)B_*H_*N_*D_];

// ---------------------------------------------------------------------------
// Kernel 1: fused QKV projection.  Y = X @ W^T + b, scattered to [b,h,n,d].
// 64x64 tile, BK=16, 256 threads, 4x4 microtile.
// ---------------------------------------------------------------------------
__global__ __launch_bounds__(256) void qkv_kernel(
    const float* __restrict__ x,
    const float* __restrict__ Wq, const float* __restrict__ bq,
    const float* __restrict__ Wk, const float* __restrict__ bk,
    const float* __restrict__ Wv, const float* __restrict__ bv)
{
    __shared__ __align__(16) float As[16][68];   // As[k][m]
    __shared__ __align__(16) float Bs[16][68];   // Bs[k][o]

    const float* W; const float* bias; float* out;
    if (blockIdx.z == 0)      { W = Wq; bias = bq; out = g_Q; }
    else if (blockIdx.z == 1) { W = Wk; bias = bk; out = g_K; }
    else                      { W = Wv; bias = bv; out = g_V; }

    const int m0 = blockIdx.x * 64;
    const int o0 = blockIdx.y * 64;
    const int tid = threadIdx.x;
    const int tx = tid & 15, ty = tid >> 4;

    float acc[4][4] = {};

    for (int k0 = 0; k0 < E_; k0 += 16) {
        // loads: thread (ty,tx) loads rows ty+16*i, k-col tx (coalesced 16/row)
        #pragma unroll
        for (int i = 0; i < 4; i++)
            As[tx][ty + 16*i] = x[(size_t)(m0 + ty + 16*i) * E_ + k0 + tx];
        #pragma unroll
        for (int i = 0; i < 4; i++)
            Bs[tx][ty + 16*i] = W[(size_t)(o0 + ty + 16*i) * E_ + k0 + tx];
        __syncthreads();

        #pragma unroll
        for (int kk = 0; kk < 16; kk++) {
            float4 a4 = *(const float4*)&As[kk][ty*4];
            float4 b4 = *(const float4*)&Bs[kk][tx*4];
            float a[4] = {a4.x, a4.y, a4.z, a4.w};
            float b[4] = {b4.x, b4.y, b4.z, b4.w};
            #pragma unroll
            for (int i = 0; i < 4; i++)
                #pragma unroll
                for (int j = 0; j < 4; j++)
                    acc[i][j] = fmaf(a[i], b[j], acc[i][j]);
        }
        __syncthreads();
    }

    // epilogue: scatter to [b,h,n,d]; this o-tile lies inside one head (64|64)
    const int h = o0 >> 6;
    #pragma unroll
    for (int i = 0; i < 4; i++) {
        int m  = m0 + ty*4 + i;
        int bb = m >> 11;            // /N_
        int n  = m & (N_ - 1);
        float4 v;
        v.x = acc[i][0] + bias[o0 + tx*4 + 0];
        v.y = acc[i][1] + bias[o0 + tx*4 + 1];
        v.z = acc[i][2] + bias[o0 + tx*4 + 2];
        v.w = acc[i][3] + bias[o0 + tx*4 + 3];
        float* dst = out + (((size_t)(bb*H_ + h)) * N_ + n) * D_ + tx*4;
        *(float4*)dst = v;
    }
}

// ---------------------------------------------------------------------------
// Kernel 2: flash-attention per (b, h, 64-query tile), online softmax.
// Distance bias fused into score epilogue.
// ---------------------------------------------------------------------------
__global__ __launch_bounds__(256) void attn_kernel(
    const float* __restrict__ dist,
    const float* __restrict__ dw_p, const float* __restrict__ db_p)
{
    extern __shared__ __align__(16) float sm[];
    float* QsT = sm;            // [64][68]  QsT[d][r]  (Q pre-scaled by 1/8)
    float* KsT = sm + 4352;     // [64][68]  KsT[d][c]
    float* Vs  = sm + 8704;     // [64][68]  Vs [c][d]
    float* PT  = sm + 13056;    // [64][68]  PT [c][r]

    const int q0 = blockIdx.x * 64;
    const int h  = blockIdx.y;
    const int b  = blockIdx.z;
    const size_t base = ((size_t)(b*H_ + h)) * N_ * D_;
    const float* Q = g_Q + base;
    const float* K = g_K + base;
    const float* V = g_V + base;
    float*       O = g_A + base;

    const float dw = *dw_p, db = *db_p;
    const int tid = threadIdx.x;
    const int tx = tid & 15, ty = tid >> 4;

    // load Q tile transposed, pre-scaled by 1/sqrt(d)
    for (int idx = tid; idx < 4096; idx += 256) {
        int r = idx >> 6, d = idx & 63;
        QsT[d*68 + r] = Q[(size_t)(q0 + r)*D_ + d] * 0.125f;
    }

    float mrow[4], lrow[4] = {0.f, 0.f, 0.f, 0.f};
    #pragma unroll
    for (int i = 0; i < 4; i++) mrow[i] = -INFINITY;
    float acc[4][4] = {};

    for (int kt = 0; kt < N_/64; kt++) {
        const int k0 = kt * 64;
        __syncthreads();   // prev P·V done (and Q tile ready on first iter)
        for (int idx = tid; idx < 4096; idx += 256) {
            int c = idx >> 6, d = idx & 63;
            float kv = K[(size_t)(k0 + c)*D_ + d];
            float vv = V[(size_t)(k0 + c)*D_ + d];
            KsT[d*68 + c] = kv;
            Vs [c*68 + d] = vv;
        }
        __syncthreads();

        // S = (Q/8) K^T
        float s[4][4] = {};
        #pragma unroll 8
        for (int d = 0; d < 64; d++) {
            float4 a4 = *(const float4*)&QsT[d*68 + ty*4];
            float4 b4 = *(const float4*)&KsT[d*68 + tx*4];
            float a[4] = {a4.x, a4.y, a4.z, a4.w};
            float bb[4] = {b4.x, b4.y, b4.z, b4.w};
            #pragma unroll
            for (int i = 0; i < 4; i++)
                #pragma unroll
                for (int j = 0; j < 4; j++)
                    s[i][j] = fmaf(a[i], bb[j], s[i][j]);
        }

        // distance bias: s += dw*dist[q][k] + db
        #pragma unroll
        for (int i = 0; i < 4; i++) {
            float4 d4 = *(const float4*)&dist[(size_t)(q0 + ty*4 + i)*N_ + k0 + tx*4];
            s[i][0] = fmaf(dw, d4.x, s[i][0] + db);
            s[i][1] = fmaf(dw, d4.y, s[i][1] + db);
            s[i][2] = fmaf(dw, d4.z, s[i][2] + db);
            s[i][3] = fmaf(dw, d4.w, s[i][3] + db);
        }

        // online softmax (row groups = 16 lanes sharing ty)
        #pragma unroll
        for (int i = 0; i < 4; i++) {
            float mt = fmaxf(fmaxf(s[i][0], s[i][1]), fmaxf(s[i][2], s[i][3]));
            #pragma unroll
            for (int o = 1; o < 16; o <<= 1)
                mt = fmaxf(mt, __shfl_xor_sync(0xffffffffu, mt, o));
            float mn   = fmaxf(mrow[i], mt);
            float corr = __expf(mrow[i] - mn);
            float ps = 0.f;
            #pragma unroll
            for (int j = 0; j < 4; j++) {
                float p = __expf(s[i][j] - mn);
                s[i][j] = p;
                ps += p;
            }
            #pragma unroll
            for (int o = 1; o < 16; o <<= 1)
                ps += __shfl_xor_sync(0xffffffffu, ps, o);
            lrow[i] = lrow[i]*corr + ps;
            mrow[i] = mn;
            #pragma unroll
            for (int j = 0; j < 4; j++) acc[i][j] *= corr;
        }

        // stage P transposed for the P·V GEMM
        #pragma unroll
        for (int i = 0; i < 4; i++)
            #pragma unroll
            for (int j = 0; j < 4; j++)
                PT[(tx*4 + j)*68 + ty*4 + i] = s[i][j];
        __syncthreads();

        // acc += P·V
        #pragma unroll 8
        for (int c = 0; c < 64; c++) {
            float4 p4 = *(const float4*)&PT[c*68 + ty*4];
            float4 v4 = *(const float4*)&Vs[c*68 + tx*4];
            float p[4] = {p4.x, p4.y, p4.z, p4.w};
            float v[4] = {v4.x, v4.y, v4.z, v4.w};
            #pragma unroll
            for (int i = 0; i < 4; i++)
                #pragma unroll
                for (int j = 0; j < 4; j++)
                    acc[i][j] = fmaf(p[i], v[j], acc[i][j]);
        }
    }

    // normalize + store to g_A [b,h,n,d]
    #pragma unroll
    for (int i = 0; i < 4; i++) {
        float inv = 1.f / lrow[i];
        float4 v;
        v.x = acc[i][0]*inv; v.y = acc[i][1]*inv;
        v.z = acc[i][2]*inv; v.w = acc[i][3]*inv;
        *(float4*)&O[(size_t)(q0 + ty*4 + i)*D_ + tx*4] = v;
    }
}

// ---------------------------------------------------------------------------
// Kernel 3: output projection.  out = A(gathered [b,n,h*d]) @ Wo^T + bo
// ---------------------------------------------------------------------------
__global__ __launch_bounds__(256) void oproj_kernel(
    const float* __restrict__ Wo, const float* __restrict__ bo,
    float* __restrict__ out)
{
    __shared__ __align__(16) float As[16][68];
    __shared__ __align__(16) float Bs[16][68];

    const int m0 = blockIdx.x * 64;
    const int o0 = blockIdx.y * 64;
    const int tid = threadIdx.x;
    const int tx = tid & 15, ty = tid >> 4;

    float acc[4][4] = {};

    for (int k0 = 0; k0 < E_; k0 += 16) {
        const int hh = k0 >> 6;          // 16-wide k-tile sits inside one head
        const int dd = (k0 & 63) + tx;
        #pragma unroll
        for (int i = 0; i < 4; i++) {
            int mm = m0 + ty + 16*i;
            int bb = mm >> 11;
            int n  = mm & (N_ - 1);
            As[tx][ty + 16*i] = g_A[(((size_t)(bb*H_ + hh)) * N_ + n) * D_ + dd];
        }
        #pragma unroll
        for (int i = 0; i < 4; i++)
            Bs[tx][ty + 16*i] = Wo[(size_t)(o0 + ty + 16*i) * E_ + k0 + tx];
        __syncthreads();

        #pragma unroll
        for (int kk = 0; kk < 16; kk++) {
            float4 a4 = *(const float4*)&As[kk][ty*4];
            float4 b4 = *(const float4*)&Bs[kk][tx*4];
            float a[4] = {a4.x, a4.y, a4.z, a4.w};
            float b[4] = {b4.x, b4.y, b4.z, b4.w};
            #pragma unroll
            for (int i = 0; i < 4; i++)
                #pragma unroll
                for (int j = 0; j < 4; j++)
                    acc[i][j] = fmaf(a[i], b[j], acc[i][j]);
        }
        __syncthreads();
    }

    #pragma unroll
    for (int i = 0; i < 4; i++) {
        int mm = m0 + ty*4 + i;
        float4 v;
        v.x = acc[i][0] + bo[o0 + tx*4 + 0];
        v.y = acc[i][1] + bo[o0 + tx*4 + 1];
        v.z = acc[i][2] + bo[o0 + tx*4 + 2];
        v.w = acc[i][3] + bo[o0 + tx*4 + 3];
        *(float4*)&out[(size_t)mm * E_ + o0 + tx*4] = v;
    }
}

// ---------------------------------------------------------------------------
extern "C" void kernel_launch(void* const* d_in, const int* in_sizes, int n_in,
                              void* d_out, int out_size)
{
    const float* x    = (const float*)d_in[0];
    const float* dist = (const float*)d_in[1];
    const float* Wq   = (const float*)d_in[2];
    const float* bq   = (const float*)d_in[3];
    const float* Wk   = (const float*)d_in[4];
    const float* bk   = (const float*)d_in[5];
    const float* Wv   = (const float*)d_in[6];
    const float* bv   = (const float*)d_in[7];
    const float* Wo   = (const float*)d_in[8];
    const float* bo   = (const float*)d_in[9];
    const float* dw   = (const float*)d_in[10];
    const float* db   = (const float*)d_in[11];
    float* out = (float*)d_out;

    qkv_kernel<<<dim3(M_/64, E_/64, 3), 256>>>(x, Wq, bq, Wk, bk, Wv, bv);

    const int shmem = 4 * 64 * 68 * (int)sizeof(float);  // 69632 B
    cudaFuncSetAttribute(attn_kernel,
                         cudaFuncAttributeMaxDynamicSharedMemorySize, shmem);
    attn_kernel<<<dim3(N_/64, H_, B_), 256, shmem>>>(dist, dw, db);

    oproj_kernel<<<dim3(M_/64, E_/64), 256>>>(Wo, bo, out);
}

// round 3
// speedup vs baseline: 1.6364x; 1.6364x over previous
#include <cuda_runtime.h>
#include <math.h>
#include <stdint.h>

#define B_ 4
#define N_ 2048
#define E_ 1024
#define H_ 16
#define D_ 64
#define M_ (B_*N_)   // 8192

// Scratch: Q,K,V,attn-out in [b,h,n,d] layout.
__device__ float g_Q[(size_t)B_*H_*N_*D_];
__device__ float g_K[(size_t)B_*H_*N_*D_];
__device__ float g_V[(size_t)B_*H_*N_*D_];
__device__ float g_A[(size_t)B_*H_*N_*D_];

// ---------------------------------------------------------------------------
// helpers
// ---------------------------------------------------------------------------
__device__ __forceinline__ uint32_t f2tf(float x) {
    uint32_t u;
    asm("cvt.rna.tf32.f32 %0, %1;" : "=r"(u) : "f"(x));
    return u;
}

__device__ __forceinline__ void mma8(float* c, const uint32_t* a, const uint32_t* b) {
    asm volatile(
        "mma.sync.aligned.m16n8k8.row.col.f32.tf32.tf32.f32 "
        "{%0,%1,%2,%3}, {%4,%5,%6,%7}, {%8,%9}, {%0,%1,%2,%3};"
        : "+f"(c[0]), "+f"(c[1]), "+f"(c[2]), "+f"(c[3])
        : "r"(a[0]), "r"(a[1]), "r"(a[2]), "r"(a[3]), "r"(b[0]), "r"(b[1]));
}

__device__ __forceinline__ float4 rnd4(float4 v) {
    float4 r;
    r.x = __uint_as_float(f2tf(v.x));
    r.y = __uint_as_float(f2tf(v.y));
    r.z = __uint_as_float(f2tf(v.z));
    r.w = __uint_as_float(f2tf(v.w));
    return r;
}

// ---------------------------------------------------------------------------
// Projection GEMM core: C[128m x 128n] = A[m,k] * W[n,k]^T + bias
// BK=32, double-buffered smem with pad-36 rows (conflict-free frag LDS).
// GATHER_A: A gathered from g_A [b,h,n,d]; SCATTER_OUT: C scattered to [b,h,n,d].
// ---------------------------------------------------------------------------
template<bool GATHER_A, bool SCATTER_OUT>
__device__ __forceinline__ void proj_core(
    const float* __restrict__ A, const float* __restrict__ W,
    const float* __restrict__ bias, float* __restrict__ outp)
{
    extern __shared__ float smf[];
    float* AsBuf = smf;            // 2 x 128*36
    float* BsBuf = smf + 9216;     // 2 x 128*36

    const int tid  = threadIdx.x;
    const int wid  = tid >> 5;
    const int lane = tid & 31;
    const int g    = lane >> 2;
    const int tg   = lane & 3;
    const int mw   = wid & 3;      // 0..3  (m direction)
    const int nw   = wid >> 2;     // 0..1  (n direction)

    const int m0 = blockIdx.x * 128;
    const int o0 = blockIdx.y * 128;

    const int lr = tid >> 3;          // 0..31 loader row
    const int lk = (tid & 7) * 4;     // 0..28 loader k (float4)

    float cacc[2][8][4] = {};
    float4 ra[4], rb[4];

    // ---- prologue: load tile 0 ----
    #pragma unroll
    for (int p = 0; p < 4; p++) {
        int m = m0 + lr + p*32;
        if (GATHER_A) {
            int bb = m >> 11, n = m & (N_-1), hh = lk >> 6, dd = lk & 63;
            ra[p] = *(const float4*)&g_A[(((size_t)(bb*H_ + hh))*N_ + n)*D_ + dd];
        } else {
            ra[p] = *(const float4*)&A[(size_t)m*E_ + lk];
        }
        rb[p] = *(const float4*)&W[(size_t)(o0 + lr + p*32)*E_ + lk];
    }
    #pragma unroll
    for (int p = 0; p < 4; p++) {
        *(float4*)&AsBuf[(lr + p*32)*36 + lk] = rnd4(ra[p]);
        *(float4*)&BsBuf[(lr + p*32)*36 + lk] = rnd4(rb[p]);
    }
    __syncthreads();

    for (int it = 0; it < 32; ++it) {
        const int cur = it & 1;
        if (it < 31) {
            const int k0 = (it + 1) * 32;
            #pragma unroll
            for (int p = 0; p < 4; p++) {
                int m = m0 + lr + p*32;
                int k = k0 + lk;
                if (GATHER_A) {
                    int bb = m >> 11, n = m & (N_-1), hh = k >> 6, dd = k & 63;
                    ra[p] = *(const float4*)&g_A[(((size_t)(bb*H_ + hh))*N_ + n)*D_ + dd];
                } else {
                    ra[p] = *(const float4*)&A[(size_t)m*E_ + k];
                }
                rb[p] = *(const float4*)&W[(size_t)(o0 + lr + p*32)*E_ + k];
            }
        }

        // ---- mma over current buffer ----
        const uint32_t* Au = (const uint32_t*)(AsBuf + cur*4608);
        const uint32_t* Bu = (const uint32_t*)(BsBuf + cur*4608);
        #pragma unroll
        for (int kb = 0; kb < 4; kb++) {
            uint32_t af[2][4];
            #pragma unroll
            for (int mi = 0; mi < 2; mi++) {
                int r0 = mw*32 + mi*16 + g;
                af[mi][0] = Au[(r0    )*36 + kb*8 + tg    ];
                af[mi][1] = Au[(r0 + 8)*36 + kb*8 + tg    ];
                af[mi][2] = Au[(r0    )*36 + kb*8 + tg + 4];
                af[mi][3] = Au[(r0 + 8)*36 + kb*8 + tg + 4];
            }
            #pragma unroll
            for (int nb = 0; nb < 8; nb++) {
                uint32_t bf[2];
                int c0 = nw*64 + nb*8 + g;
                bf[0] = Bu[c0*36 + kb*8 + tg    ];
                bf[1] = Bu[c0*36 + kb*8 + tg + 4];
                mma8(cacc[0][nb], af[0], bf);
                mma8(cacc[1][nb], af[1], bf);
            }
        }

        if (it < 31) {
            const int nxt = cur ^ 1;
            #pragma unroll
            for (int p = 0; p < 4; p++) {
                *(float4*)&AsBuf[nxt*4608 + (lr + p*32)*36 + lk] = rnd4(ra[p]);
                *(float4*)&BsBuf[nxt*4608 + (lr + p*32)*36 + lk] = rnd4(rb[p]);
            }
            __syncthreads();
        }
    }

    // ---- epilogue ----
    #pragma unroll
    for (int mi = 0; mi < 2; mi++) {
        int r0 = m0 + mw*32 + mi*16 + g;
        #pragma unroll
        for (int nb = 0; nb < 8; nb++) {
            int gcol = o0 + nw*64 + nb*8 + 2*tg;
            float b0 = bias[gcol], b1 = bias[gcol + 1];
            float2 v0 = { cacc[mi][nb][0] + b0, cacc[mi][nb][1] + b1 };
            float2 v1 = { cacc[mi][nb][2] + b0, cacc[mi][nb][3] + b1 };
            if (SCATTER_OUT) {
                int hh = gcol >> 6, dd = gcol & 63;
                int bb0 = r0 >> 11, n0 = r0 & (N_-1);
                int r1 = r0 + 8;
                int bb1 = r1 >> 11, n1 = r1 & (N_-1);
                *(float2*)&outp[(((size_t)(bb0*H_ + hh))*N_ + n0)*D_ + dd] = v0;
                *(float2*)&outp[(((size_t)(bb1*H_ + hh))*N_ + n1)*D_ + dd] = v1;
            } else {
                *(float2*)&outp[(size_t)r0*E_ + gcol] = v0;
                *(float2*)&outp[(size_t)(r0 + 8)*E_ + gcol] = v1;
            }
        }
    }
}

__global__ __launch_bounds__(256) void qkv_tc(
    const float* __restrict__ x,
    const float* __restrict__ Wq, const float* __restrict__ bq,
    const float* __restrict__ Wk, const float* __restrict__ bk,
    const float* __restrict__ Wv, const float* __restrict__ bv)
{
    const float* W; const float* bias; float* out;
    if (blockIdx.z == 0)      { W = Wq; bias = bq; out = g_Q; }
    else if (blockIdx.z == 1) { W = Wk; bias = bk; out = g_K; }
    else                      { W = Wv; bias = bv; out = g_V; }
    proj_core<false, true>(x, W, bias, out);
}

__global__ __launch_bounds__(256) void oproj_tc(
    const float* __restrict__ Wo, const float* __restrict__ bo,
    float* __restrict__ out)
{
    proj_core<true, false>(nullptr, Wo, bo, out);
}

// ---------------------------------------------------------------------------
// Attention: per (b, h, 128-q tile). 8 warps x 16 q-rows. kv tiles of 64.
// Q frags in registers; S and P*V via mma tf32; online softmax on C frags.
// ---------------------------------------------------------------------------
__global__ __launch_bounds__(256) void attn_tc(
    const float* __restrict__ dist,
    const float* __restrict__ dwp, const float* __restrict__ dbp)
{
    extern __shared__ float smf[];
    float* Ks = smf;               // [64][68]
    float* Vs = smf + 4352;        // [64][68]
    // per-warp P tile [16][68]
    const int tid  = threadIdx.x;
    const int wid  = tid >> 5;
    const int lane = tid & 31;
    const int g    = lane >> 2;
    const int tg   = lane & 3;
    float* Ps = smf + 8704 + wid * 1088;

    const int q0 = blockIdx.x * 128;
    const int h  = blockIdx.y;
    const int b  = blockIdx.z;
    const size_t base = ((size_t)(b*H_ + h)) * N_ * D_;
    const float* Qp = g_Q + base;
    const float* Kp = g_K + base;
    const float* Vp = g_V + base;
    float*       Op = g_A + base;

    const float dw = dwp[0], db = dbp[0];
    const int wrow = wid * 16;
    const int qr0 = q0 + wrow + g;
    const int qr1 = qr0 + 8;

    // Q fragments in registers, pre-scaled by 1/sqrt(d)=0.125
    uint32_t qa[8][4];
    #pragma unroll
    for (int kb = 0; kb < 8; kb++) {
        int c = kb*8 + tg;
        qa[kb][0] = f2tf(0.125f * Qp[(size_t)qr0*D_ + c    ]);
        qa[kb][1] = f2tf(0.125f * Qp[(size_t)qr1*D_ + c    ]);
        qa[kb][2] = f2tf(0.125f * Qp[(size_t)qr0*D_ + c + 4]);
        qa[kb][3] = f2tf(0.125f * Qp[(size_t)qr1*D_ + c + 4]);
    }

    float oc[8][4] = {};
    float mh0 = -INFINITY, mh1 = -INFINITY;
    float lh0 = 0.f, lh1 = 0.f;

    const int lrow = tid >> 2;         // 0..63
    const int lc   = (tid & 3) * 16;   // 0,16,32,48

    for (int kt = 0; kt < 32; kt++) {
        const int kv0 = kt * 64;
        __syncthreads();
        #pragma unroll
        for (int j = 0; j < 4; j++) {
            float4 kv = *(const float4*)&Kp[(size_t)(kv0 + lrow)*D_ + lc + 4*j];
            float4 vv = *(const float4*)&Vp[(size_t)(kv0 + lrow)*D_ + lc + 4*j];
            *(float4*)&Ks[lrow*68 + lc + 4*j] = rnd4(kv);
            *(float4*)&Vs[lrow*68 + lc + 4*j] = rnd4(vv);
        }
        __syncthreads();

        // ---- S = (Q/8) K^T ----
        const uint32_t* Ku = (const uint32_t*)Ks;
        float sc[8][4] = {};
        #pragma unroll
        for (int kb = 0; kb < 8; kb++) {
            #pragma unroll
            for (int nb = 0; nb < 8; nb++) {
                uint32_t bf[2];
                bf[0] = Ku[(nb*8 + g)*68 + kb*8 + tg    ];
                bf[1] = Ku[(nb*8 + g)*68 + kb*8 + tg + 4];
                mma8(sc[nb], qa[kb], bf);
            }
        }

        // ---- distance bias ----
        #pragma unroll
        for (int nb = 0; nb < 8; nb++) {
            int col = kv0 + nb*8 + 2*tg;
            float2 d0 = *(const float2*)&dist[(size_t)qr0*N_ + col];
            float2 d1 = *(const float2*)&dist[(size_t)qr1*N_ + col];
            sc[nb][0] = fmaf(dw, d0.x, sc[nb][0] + db);
            sc[nb][1] = fmaf(dw, d0.y, sc[nb][1] + db);
            sc[nb][2] = fmaf(dw, d1.x, sc[nb][2] + db);
            sc[nb][3] = fmaf(dw, d1.y, sc[nb][3] + db);
        }

        // ---- online softmax (rows g / g+8, stats shared across lane quad) ----
        float mt0 = -INFINITY, mt1 = -INFINITY;
        #pragma unroll
        for (int nb = 0; nb < 8; nb++) {
            mt0 = fmaxf(mt0, fmaxf(sc[nb][0], sc[nb][1]));
            mt1 = fmaxf(mt1, fmaxf(sc[nb][2], sc[nb][3]));
        }
        mt0 = fmaxf(mt0, __shfl_xor_sync(0xffffffffu, mt0, 1));
        mt0 = fmaxf(mt0, __shfl_xor_sync(0xffffffffu, mt0, 2));
        mt1 = fmaxf(mt1, __shfl_xor_sync(0xffffffffu, mt1, 1));
        mt1 = fmaxf(mt1, __shfl_xor_sync(0xffffffffu, mt1, 2));
        float mn0 = fmaxf(mh0, mt0), mn1 = fmaxf(mh1, mt1);
        float corr0 = __expf(mh0 - mn0), corr1 = __expf(mh1 - mn1);
        float s0 = 0.f, s1 = 0.f;
        #pragma unroll
        for (int nb = 0; nb < 8; nb++) {
            sc[nb][0] = __expf(sc[nb][0] - mn0); s0 += sc[nb][0];
            sc[nb][1] = __expf(sc[nb][1] - mn0); s0 += sc[nb][1];
            sc[nb][2] = __expf(sc[nb][2] - mn1); s1 += sc[nb][2];
            sc[nb][3] = __expf(sc[nb][3] - mn1); s1 += sc[nb][3];
        }
        s0 += __shfl_xor_sync(0xffffffffu, s0, 1);
        s0 += __shfl_xor_sync(0xffffffffu, s0, 2);
        s1 += __shfl_xor_sync(0xffffffffu, s1, 1);
        s1 += __shfl_xor_sync(0xffffffffu, s1, 2);
        lh0 = lh0*corr0 + s0;
        lh1 = lh1*corr1 + s1;
        mh0 = mn0; mh1 = mn1;
        #pragma unroll
        for (int nb = 0; nb < 8; nb++) {
            oc[nb][0] *= corr0; oc[nb][1] *= corr0;
            oc[nb][2] *= corr1; oc[nb][3] *= corr1;
        }

        // ---- stage P (tf32-rounded) into per-warp smem ----
        #pragma unroll
        for (int nb = 0; nb < 8; nb++) {
            float2 p01 = { __uint_as_float(f2tf(sc[nb][0])),
                           __uint_as_float(f2tf(sc[nb][1])) };
            float2 p23 = { __uint_as_float(f2tf(sc[nb][2])),
                           __uint_as_float(f2tf(sc[nb][3])) };
            *(float2*)&Ps[(g    )*68 + nb*8 + 2*tg] = p01;
            *(float2*)&Ps[(g + 8)*68 + nb*8 + 2*tg] = p23;
        }
        __syncwarp();

        // ---- O += P V ----
        const uint32_t* Pu = (const uint32_t*)Ps;
        const uint32_t* Vu = (const uint32_t*)Vs;
        #pragma unroll
        for (int kb = 0; kb < 8; kb++) {
            uint32_t af[4];
            af[0] = Pu[(g    )*68 + kb*8 + tg    ];
            af[1] = Pu[(g + 8)*68 + kb*8 + tg    ];
            af[2] = Pu[(g    )*68 + kb*8 + tg + 4];
            af[3] = Pu[(g + 8)*68 + kb*8 + tg + 4];
            #pragma unroll
            for (int nb = 0; nb < 8; nb++) {
                uint32_t bf[2];
                bf[0] = Vu[(kb*8 + tg    )*68 + nb*8 + g];
                bf[1] = Vu[(kb*8 + tg + 4)*68 + nb*8 + g];
                mma8(oc[nb], af, bf);
            }
        }
        __syncwarp();
    }

    const float inv0 = 1.f / lh0, inv1 = 1.f / lh1;
    #pragma unroll
    for (int nb = 0; nb < 8; nb++) {
        int c = nb*8 + 2*tg;
        float2 v0 = { oc[nb][0]*inv0, oc[nb][1]*inv0 };
        float2 v1 = { oc[nb][2]*inv1, oc[nb][3]*inv1 };
        *(float2*)&Op[(size_t)qr0*D_ + c] = v0;
        *(float2*)&Op[(size_t)qr1*D_ + c] = v1;
    }
}

// ---------------------------------------------------------------------------
extern "C" void kernel_launch(void* const* d_in, const int* in_sizes, int n_in,
                              void* d_out, int out_size)
{
    const float* x    = (const float*)d_in[0];
    const float* dist = (const float*)d_in[1];
    const float* Wq   = (const float*)d_in[2];
    const float* bq   = (const float*)d_in[3];
    const float* Wk   = (const float*)d_in[4];
    const float* bk   = (const float*)d_in[5];
    const float* Wv   = (const float*)d_in[6];
    const float* bv   = (const float*)d_in[7];
    const float* Wo   = (const float*)d_in[8];
    const float* bo   = (const float*)d_in[9];
    const float* dw   = (const float*)d_in[10];
    const float* db   = (const float*)d_in[11];
    float* out = (float*)d_out;

    const int proj_smem = 2 * 9216 * (int)sizeof(float);   // 73728 B
    const int attn_smem = 17408 * (int)sizeof(float);      // 69632 B
    cudaFuncSetAttribute(qkv_tc,  cudaFuncAttributeMaxDynamicSharedMemorySize, proj_smem);
    cudaFuncSetAttribute(oproj_tc, cudaFuncAttributeMaxDynamicSharedMemorySize, proj_smem);
    cudaFuncSetAttribute(attn_tc, cudaFuncAttributeMaxDynamicSharedMemorySize, attn_smem);

    qkv_tc<<<dim3(M_/128, E_/128, 3), 256, proj_smem>>>(x, Wq, bq, Wk, bk, Wv, bv);
    attn_tc<<<dim3(N_/128, H_, B_), 256, attn_smem>>>(dist, dw, db);
    oproj_tc<<<dim3(M_/128, E_/128), 256, proj_smem>>>(Wo, bo, out);
}

// round 5
// speedup vs baseline: 2.9921x; 1.8285x over previous
#include <cuda_runtime.h>
#include <math.h>
#include <stdint.h>

#define B_ 4
#define N_ 2048
#define E_ 1024
#define H_ 16
#define D_ 64
#define M_ (B_*N_)   // 8192

// Scratch
__device__ float g_Q[(size_t)B_*H_*N_*D_];
__device__ float g_K[(size_t)B_*H_*N_*D_];
__device__ float g_V[(size_t)B_*H_*N_*D_];
__device__ float g_A[(size_t)B_*H_*N_*D_];
__device__ float g_X[(size_t)M_*E_];          // pre-rounded x
__device__ float g_Wq[(size_t)E_*E_];
__device__ float g_Wk[(size_t)E_*E_];
__device__ float g_Wv[(size_t)E_*E_];
__device__ float g_Wo[(size_t)E_*E_];

// ---------------------------------------------------------------------------
// helpers
// ---------------------------------------------------------------------------
__device__ __forceinline__ uint32_t f2tf(float x) {
    uint32_t u;
    asm("cvt.rna.tf32.f32 %0, %1;" : "=r"(u) : "f"(x));
    return u;
}
__device__ __forceinline__ float rndf(float x) { return __uint_as_float(f2tf(x)); }

__device__ __forceinline__ void mma8(float* c, const uint32_t* a, const uint32_t* b) {
    asm volatile(
        "mma.sync.aligned.m16n8k8.row.col.f32.tf32.tf32.f32 "
        "{%0,%1,%2,%3}, {%4,%5,%6,%7}, {%8,%9}, {%0,%1,%2,%3};"
        : "+f"(c[0]), "+f"(c[1]), "+f"(c[2]), "+f"(c[3])
        : "r"(a[0]), "r"(a[1]), "r"(a[2]), "r"(a[3]), "r"(b[0]), "r"(b[1]));
}

__device__ __forceinline__ uint32_t smem_u32(const void* p) {
    uint32_t a;
    asm("{ .reg .u64 t; cvta.to.shared.u64 t, %1; cvt.u32.u64 %0, t; }" : "=r"(a) : "l"(p));
    return a;
}
__device__ __forceinline__ void cp16(uint32_t dst, const void* src) {
    size_t g = __cvta_generic_to_global(src);
    asm volatile("cp.async.cg.shared.global [%0], [%1], 16;" :: "r"(dst), "l"(g));
}
#define CP_COMMIT() asm volatile("cp.async.commit_group;" ::: "memory")
#define CP_WAIT0()  asm volatile("cp.async.wait_group 0;" ::: "memory")
#define CP_WAIT1()  asm volatile("cp.async.wait_group 1;" ::: "memory")

// ---------------------------------------------------------------------------
// Pre-round pass: dst = tf32_round(src)
// ---------------------------------------------------------------------------
__global__ void round_pass(const float* __restrict__ src, float* __restrict__ dst, int n4) {
    int i = blockIdx.x * blockDim.x + threadIdx.x;
    if (i < n4) {
        float4 v = ((const float4*)src)[i];
        v.x = rndf(v.x); v.y = rndf(v.y); v.z = rndf(v.z); v.w = rndf(v.w);
        ((float4*)dst)[i] = v;
    }
}

// ---------------------------------------------------------------------------
// Projection GEMM core: C[128m x 128n] = A[m,k] * W[n,k]^T + bias
// 3-stage cp.async ring, BK=32, pad-36 rows.
// ---------------------------------------------------------------------------
template<bool GATHER_A, bool SCATTER_OUT>
__device__ __forceinline__ void proj_core(
    const float* __restrict__ Ap, const float* __restrict__ Wp,
    const float* __restrict__ bias, float* __restrict__ outp,
    float oscale, bool oround)
{
    extern __shared__ float smf[];
    float* AsBuf = smf;              // 3 x 4608
    float* BsBuf = smf + 13824;      // 3 x 4608
    const uint32_t As_u = smem_u32(AsBuf);
    const uint32_t Bs_u = smem_u32(BsBuf);

    const int tid  = threadIdx.x;
    const int wid  = tid >> 5;
    const int lane = tid & 31;
    const int g    = lane >> 2;
    const int tg   = lane & 3;
    const int mw   = wid & 3;
    const int nw   = wid >> 2;

    const int m0 = blockIdx.x * 128;
    const int o0 = blockIdx.y * 128;

    const int lr = tid >> 3;          // 0..31
    const int lk = (tid & 7) * 4;     // 0..28

    auto issue = [&](int it, int st) {
        const int k = it * 32 + lk;
        #pragma unroll
        for (int p = 0; p < 4; p++) {
            const int row = lr + p * 32;
            const float* sa;
            if (GATHER_A) {
                int m = m0 + row, bb = m >> 11, n = m & (N_-1);
                int hh = k >> 6, dd = k & 63;
                sa = &g_A[(((size_t)(bb*H_ + hh))*N_ + n)*D_ + dd];
            } else {
                sa = &Ap[(size_t)(m0 + row)*E_ + k];
            }
            cp16(As_u + (uint32_t)(st*18432) + (uint32_t)((row*36 + lk)*4), sa);
            cp16(Bs_u + (uint32_t)(st*18432) + (uint32_t)((row*36 + lk)*4),
                 &Wp[(size_t)(o0 + row)*E_ + k]);
        }
        CP_COMMIT();
    };

    float cacc[2][8][4] = {};

    issue(0, 0);
    issue(1, 1);

    int st = 0;
    for (int it = 0; it < 32; ++it) {
        if (it == 31) CP_WAIT0(); else CP_WAIT1();
        __syncthreads();
        if (it + 2 < 32) {
            int st2 = st + 2; if (st2 >= 3) st2 -= 3;
            issue(it + 2, st2);
        }

        const uint32_t* Au = (const uint32_t*)(AsBuf + st*4608);
        const uint32_t* Bu = (const uint32_t*)(BsBuf + st*4608);
        #pragma unroll
        for (int kb = 0; kb < 4; kb++) {
            uint32_t af[2][4];
            #pragma unroll
            for (int mi = 0; mi < 2; mi++) {
                int r0 = mw*32 + mi*16 + g;
                af[mi][0] = Au[(r0    )*36 + kb*8 + tg    ];
                af[mi][1] = Au[(r0 + 8)*36 + kb*8 + tg    ];
                af[mi][2] = Au[(r0    )*36 + kb*8 + tg + 4];
                af[mi][3] = Au[(r0 + 8)*36 + kb*8 + tg + 4];
            }
            #pragma unroll
            for (int nb = 0; nb < 8; nb++) {
                uint32_t bf[2];
                int c0 = nw*64 + nb*8 + g;
                bf[0] = Bu[c0*36 + kb*8 + tg    ];
                bf[1] = Bu[c0*36 + kb*8 + tg + 4];
                mma8(cacc[0][nb], af[0], bf);
                mma8(cacc[1][nb], af[1], bf);
            }
        }
        if (++st == 3) st = 0;
    }

    // ---- epilogue ----
    #pragma unroll
    for (int mi = 0; mi < 2; mi++) {
        int r0 = m0 + mw*32 + mi*16 + g;
        #pragma unroll
        for (int nb = 0; nb < 8; nb++) {
            int gcol = o0 + nw*64 + nb*8 + 2*tg;
            float b0 = bias[gcol], b1 = bias[gcol + 1];
            float2 v0 = { (cacc[mi][nb][0] + b0)*oscale, (cacc[mi][nb][1] + b1)*oscale };
            float2 v1 = { (cacc[mi][nb][2] + b0)*oscale, (cacc[mi][nb][3] + b1)*oscale };
            if (oround) {
                v0.x = rndf(v0.x); v0.y = rndf(v0.y);
                v1.x = rndf(v1.x); v1.y = rndf(v1.y);
            }
            if (SCATTER_OUT) {
                int hh = gcol >> 6, dd = gcol & 63;
                int bb0 = r0 >> 11, n0 = r0 & (N_-1);
                int r1 = r0 + 8, bb1 = r1 >> 11, n1 = r1 & (N_-1);
                *(float2*)&outp[(((size_t)(bb0*H_ + hh))*N_ + n0)*D_ + dd] = v0;
                *(float2*)&outp[(((size_t)(bb1*H_ + hh))*N_ + n1)*D_ + dd] = v1;
            } else {
                *(float2*)&outp[(size_t)r0*E_ + gcol] = v0;
                *(float2*)&outp[(size_t)(r0 + 8)*E_ + gcol] = v1;
            }
        }
    }
}

__global__ __launch_bounds__(256) void qkv_tc()
{
    const float* W; float* out; float sc;
    if (blockIdx.z == 0)      { W = g_Wq; out = g_Q; sc = 0.125f; }
    else if (blockIdx.z == 1) { W = g_Wk; out = g_K; sc = 1.f; }
    else                      { W = g_Wv; out = g_V; sc = 1.f; }
    proj_core<false, true>(g_X, W, /*bias later*/ nullptr, out, sc, true);
}

// biases must come from inputs; wrap with explicit pointers instead:
__global__ __launch_bounds__(256) void qkv_tc2(
    const float* __restrict__ bq, const float* __restrict__ bk,
    const float* __restrict__ bv)
{
    const float* W; const float* bias; float* out; float sc;
    if (blockIdx.z == 0)      { W = g_Wq; bias = bq; out = g_Q; sc = 0.125f; }
    else if (blockIdx.z == 1) { W = g_Wk; bias = bk; out = g_K; sc = 1.f; }
    else                      { W = g_Wv; bias = bv; out = g_V; sc = 1.f; }
    proj_core<false, true>(g_X, W, bias, out, sc, true);
}

__global__ __launch_bounds__(256) void oproj_tc(
    const float* __restrict__ bo, float* __restrict__ out)
{
    proj_core<true, false>(nullptr, g_Wo, bo, out, 1.f, false);
}

// ---------------------------------------------------------------------------
// Attention: per (b, h, 128-q tile). 8 warps x 16 q-rows. kv tiles of 64,
// 2-stage cp.async ring. Q pre-scaled+pre-rounded in g_Q; K/V pre-rounded.
// ---------------------------------------------------------------------------
__global__ __launch_bounds__(256) void attn_tc(
    const float* __restrict__ dist,
    const float* __restrict__ dwp, const float* __restrict__ dbp)
{
    extern __shared__ float smf[];
    // stage s: K at s*8704, V at s*8704+4352 ; Ps at 17408 + wid*1088
    const uint32_t sm_u = smem_u32(smf);

    const int tid  = threadIdx.x;
    const int wid  = tid >> 5;
    const int lane = tid & 31;
    const int g    = lane >> 2;
    const int tg   = lane & 3;
    float* Ps = smf + 17408 + wid * 1088;

    const int q0 = blockIdx.x * 128;
    const int h  = blockIdx.y;
    const int b  = blockIdx.z;
    const size_t base = ((size_t)(b*H_ + h)) * N_ * D_;
    const float* Qp = g_Q + base;
    const float* Kp = g_K + base;
    const float* Vp = g_V + base;
    float*       Op = g_A + base;

    const float dw = dwp[0], db = dbp[0];
    const int qr0 = q0 + wid*16 + g;
    const int qr1 = qr0 + 8;

    const int lrow = tid >> 2;         // 0..63
    const int lc   = (tid & 3) * 16;   // float offset

    auto issue_kv = [&](int kt, int stg) {
        const int kv0 = kt * 64;
        const uint32_t kb_u = sm_u + (uint32_t)(stg * 34816);
        #pragma unroll
        for (int j = 0; j < 4; j++) {
            cp16(kb_u          + (uint32_t)((lrow*68 + lc + 4*j)*4),
                 &Kp[(size_t)(kv0 + lrow)*D_ + lc + 4*j]);
            cp16(kb_u + 17408u + (uint32_t)((lrow*68 + lc + 4*j)*4),
                 &Vp[(size_t)(kv0 + lrow)*D_ + lc + 4*j]);
        }
        CP_COMMIT();
    };

    // Q fragments (already tf32-rounded & 0.125-scaled)
    uint32_t qa[8][4];
    #pragma unroll
    for (int kb = 0; kb < 8; kb++) {
        int c = kb*8 + tg;
        qa[kb][0] = __float_as_uint(Qp[(size_t)qr0*D_ + c    ]);
        qa[kb][1] = __float_as_uint(Qp[(size_t)qr1*D_ + c    ]);
        qa[kb][2] = __float_as_uint(Qp[(size_t)qr0*D_ + c + 4]);
        qa[kb][3] = __float_as_uint(Qp[(size_t)qr1*D_ + c + 4]);
    }

    float oc[8][4] = {};
    float mh0 = -INFINITY, mh1 = -INFINITY;
    float lh0 = 0.f, lh1 = 0.f;

    issue_kv(0, 0);

    for (int kt = 0; kt < 32; kt++) {
        const int kv0 = kt * 64;
        const int stg = kt & 1;
        CP_WAIT0();
        __syncthreads();
        if (kt + 1 < 32) issue_kv(kt + 1, stg ^ 1);

        const uint32_t* Ku = (const uint32_t*)(smf + stg*8704);
        const uint32_t* Vu = (const uint32_t*)(smf + stg*8704 + 4352);

        // ---- S = (Q/8) K^T ----
        float sc[8][4] = {};
        #pragma unroll
        for (int kb = 0; kb < 8; kb++) {
            #pragma unroll
            for (int nb = 0; nb < 8; nb++) {
                uint32_t bf[2];
                bf[0] = Ku[(nb*8 + g)*68 + kb*8 + tg    ];
                bf[1] = Ku[(nb*8 + g)*68 + kb*8 + tg + 4];
                mma8(sc[nb], qa[kb], bf);
            }
        }

        // ---- distance bias ----
        #pragma unroll
        for (int nb = 0; nb < 8; nb++) {
            int col = kv0 + nb*8 + 2*tg;
            float2 d0 = *(const float2*)&dist[(size_t)qr0*N_ + col];
            float2 d1 = *(const float2*)&dist[(size_t)qr1*N_ + col];
            sc[nb][0] = fmaf(dw, d0.x, sc[nb][0] + db);
            sc[nb][1] = fmaf(dw, d0.y, sc[nb][1] + db);
            sc[nb][2] = fmaf(dw, d1.x, sc[nb][2] + db);
            sc[nb][3] = fmaf(dw, d1.y, sc[nb][3] + db);
        }

        // ---- online softmax ----
        float mt0 = -INFINITY, mt1 = -INFINITY;
        #pragma unroll
        for (int nb = 0; nb < 8; nb++) {
            mt0 = fmaxf(mt0, fmaxf(sc[nb][0], sc[nb][1]));
            mt1 = fmaxf(mt1, fmaxf(sc[nb][2], sc[nb][3]));
        }
        mt0 = fmaxf(mt0, __shfl_xor_sync(0xffffffffu, mt0, 1));
        mt0 = fmaxf(mt0, __shfl_xor_sync(0xffffffffu, mt0, 2));
        mt1 = fmaxf(mt1, __shfl_xor_sync(0xffffffffu, mt1, 1));
        mt1 = fmaxf(mt1, __shfl_xor_sync(0xffffffffu, mt1, 2));
        float mn0 = fmaxf(mh0, mt0), mn1 = fmaxf(mh1, mt1);
        float corr0 = __expf(mh0 - mn0), corr1 = __expf(mh1 - mn1);
        float s0 = 0.f, s1 = 0.f;
        #pragma unroll
        for (int nb = 0; nb < 8; nb++) {
            sc[nb][0] = __expf(sc[nb][0] - mn0); s0 += sc[nb][0];
            sc[nb][1] = __expf(sc[nb][1] - mn0); s0 += sc[nb][1];
            sc[nb][2] = __expf(sc[nb][2] - mn1); s1 += sc[nb][2];
            sc[nb][3] = __expf(sc[nb][3] - mn1); s1 += sc[nb][3];
        }
        s0 += __shfl_xor_sync(0xffffffffu, s0, 1);
        s0 += __shfl_xor_sync(0xffffffffu, s0, 2);
        s1 += __shfl_xor_sync(0xffffffffu, s1, 1);
        s1 += __shfl_xor_sync(0xffffffffu, s1, 2);
        lh0 = lh0*corr0 + s0;
        lh1 = lh1*corr1 + s1;
        mh0 = mn0; mh1 = mn1;
        #pragma unroll
        for (int nb = 0; nb < 8; nb++) {
            oc[nb][0] *= corr0; oc[nb][1] *= corr0;
            oc[nb][2] *= corr1; oc[nb][3] *= corr1;
        }

        // ---- stage P (tf32) into per-warp smem ----
        #pragma unroll
        for (int nb = 0; nb < 8; nb++) {
            float2 p01 = { rndf(sc[nb][0]), rndf(sc[nb][1]) };
            float2 p23 = { rndf(sc[nb][2]), rndf(sc[nb][3]) };
            *(float2*)&Ps[(g    )*68 + nb*8 + 2*tg] = p01;
            *(float2*)&Ps[(g + 8)*68 + nb*8 + 2*tg] = p23;
        }
        __syncwarp();

        // ---- O += P V ----
        const uint32_t* Pu = (const uint32_t*)Ps;
        #pragma unroll
        for (int kb = 0; kb < 8; kb++) {
            uint32_t af[4];
            af[0] = Pu[(g    )*68 + kb*8 + tg    ];
            af[1] = Pu[(g + 8)*68 + kb*8 + tg    ];
            af[2] = Pu[(g    )*68 + kb*8 + tg + 4];
            af[3] = Pu[(g + 8)*68 + kb*8 + tg + 4];
            #pragma unroll
            for (int nb = 0; nb < 8; nb++) {
                uint32_t bf[2];
                bf[0] = Vu[(kb*8 + tg    )*68 + nb*8 + g];
                bf[1] = Vu[(kb*8 + tg + 4)*68 + nb*8 + g];
                mma8(oc[nb], af, bf);
            }
        }
        __syncwarp();
    }

    const float inv0 = 1.f / lh0, inv1 = 1.f / lh1;
    #pragma unroll
    for (int nb = 0; nb < 8; nb++) {
        int c = nb*8 + 2*tg;
        float2 v0 = { rndf(oc[nb][0]*inv0), rndf(oc[nb][1]*inv0) };
        float2 v1 = { rndf(oc[nb][2]*inv1), rndf(oc[nb][3]*inv1) };
        *(float2*)&Op[(size_t)qr0*D_ + c] = v0;
        *(float2*)&Op[(size_t)qr1*D_ + c] = v1;
    }
}

// ---------------------------------------------------------------------------
extern "C" void kernel_launch(void* const* d_in, const int* in_sizes, int n_in,
                              void* d_out, int out_size)
{
    const float* x    = (const float*)d_in[0];
    const float* dist = (const float*)d_in[1];
    const float* Wq   = (const float*)d_in[2];
    const float* bq   = (const float*)d_in[3];
    const float* Wk   = (const float*)d_in[4];
    const float* bk   = (const float*)d_in[5];
    const float* Wv   = (const float*)d_in[6];
    const float* bv   = (const float*)d_in[7];
    const float* Wo   = (const float*)d_in[8];
    const float* bo   = (const float*)d_in[9];
    const float* dw   = (const float*)d_in[10];
    const float* db   = (const float*)d_in[11];
    float* out = (float*)d_out;

    float* gx;  cudaGetSymbolAddress((void**)&gx,  g_X);
    float* gwq; cudaGetSymbolAddress((void**)&gwq, g_Wq);
    float* gwk; cudaGetSymbolAddress((void**)&gwk, g_Wk);
    float* gwv; cudaGetSymbolAddress((void**)&gwv, g_Wv);
    float* gwo; cudaGetSymbolAddress((void**)&gwo, g_Wo);

    const int nx4 = M_*E_/4, nw4 = E_*E_/4;
    round_pass<<<(nx4 + 255)/256, 256>>>(x,  gx,  nx4);
    round_pass<<<(nw4 + 255)/256, 256>>>(Wq, gwq, nw4);
    round_pass<<<(nw4 + 255)/256, 256>>>(Wk, gwk, nw4);
    round_pass<<<(nw4 + 255)/256, 256>>>(Wv, gwv, nw4);
    round_pass<<<(nw4 + 255)/256, 256>>>(Wo, gwo, nw4);

    const int proj_smem = 27648 * (int)sizeof(float);   // 110592 B
    const int attn_smem = 26112 * (int)sizeof(float);   // 104448 B
    cudaFuncSetAttribute(qkv_tc2, cudaFuncAttributeMaxDynamicSharedMemorySize, proj_smem);
    cudaFuncSetAttribute(oproj_tc, cudaFuncAttributeMaxDynamicSharedMemorySize, proj_smem);
    cudaFuncSetAttribute(attn_tc, cudaFuncAttributeMaxDynamicSharedMemorySize, attn_smem);

    qkv_tc2<<<dim3(M_/128, E_/128, 3), 256, proj_smem>>>(bq, bk, bv);
    attn_tc<<<dim3(N_/128, H_, B_), 256, attn_smem>>>(dist, dw, db);
    oproj_tc<<<dim3(M_/128, E_/128), 256, proj_smem>>>(bo, out);
}

// round 6
// speedup vs baseline: 3.0237x; 1.0106x over previous
#include <cuda_runtime.h>
#include <math.h>
#include <stdint.h>

#define B_ 4
#define N_ 2048
#define E_ 1024
#define H_ 16
#define D_ 64
#define M_ (B_*N_)   // 8192

// Scratch
__device__ float g_Q[(size_t)B_*H_*N_*D_];
__device__ float g_K[(size_t)B_*H_*N_*D_];
__device__ float g_V[(size_t)B_*H_*N_*D_];
__device__ float g_A[(size_t)B_*H_*N_*D_];
__device__ float g_X[(size_t)M_*E_];          // pre-rounded x
__device__ float g_W4[4][(size_t)E_*E_];      // pre-rounded Wq,Wk,Wv,Wo

// ---------------------------------------------------------------------------
// helpers
// ---------------------------------------------------------------------------
__device__ __forceinline__ uint32_t f2tf(float x) {
    uint32_t u;
    asm("cvt.rna.tf32.f32 %0, %1;" : "=r"(u) : "f"(x));
    return u;
}
__device__ __forceinline__ float rndf(float x) { return __uint_as_float(f2tf(x)); }

__device__ __forceinline__ void mma8(float* c, const uint32_t* a, const uint32_t* b) {
    asm volatile(
        "mma.sync.aligned.m16n8k8.row.col.f32.tf32.tf32.f32 "
        "{%0,%1,%2,%3}, {%4,%5,%6,%7}, {%8,%9}, {%0,%1,%2,%3};"
        : "+f"(c[0]), "+f"(c[1]), "+f"(c[2]), "+f"(c[3])
        : "r"(a[0]), "r"(a[1]), "r"(a[2]), "r"(a[3]), "r"(b[0]), "r"(b[1]));
}

__device__ __forceinline__ uint32_t smem_u32(const void* p) {
    uint32_t a;
    asm("{ .reg .u64 t; cvta.to.shared.u64 t, %1; cvt.u32.u64 %0, t; }" : "=r"(a) : "l"(p));
    return a;
}
__device__ __forceinline__ void cp16(uint32_t dst, const void* src) {
    size_t g = __cvta_generic_to_global(src);
    asm volatile("cp.async.cg.shared.global [%0], [%1], 16;" :: "r"(dst), "l"(g));
}
#define CP_COMMIT() asm volatile("cp.async.commit_group;" ::: "memory")
#define CP_WAIT0()  asm volatile("cp.async.wait_group 0;" ::: "memory")
#define CP_WAIT1()  asm volatile("cp.async.wait_group 1;" ::: "memory")

// ---------------------------------------------------------------------------
// Pre-round passes
// ---------------------------------------------------------------------------
__global__ void round_x(const float* __restrict__ src, int n4) {
    int i = blockIdx.x * blockDim.x + threadIdx.x;
    if (i < n4) {
        float4 v = ((const float4*)src)[i];
        v.x = rndf(v.x); v.y = rndf(v.y); v.z = rndf(v.z); v.w = rndf(v.w);
        ((float4*)g_X)[i] = v;
    }
}

__global__ void round_w(const float* __restrict__ wq, const float* __restrict__ wk,
                        const float* __restrict__ wv, const float* __restrict__ wo) {
    const float* src;
    switch (blockIdx.y) {
        case 0: src = wq; break;
        case 1: src = wk; break;
        case 2: src = wv; break;
        default: src = wo; break;
    }
    int i = blockIdx.x * blockDim.x + threadIdx.x;
    float4 v = ((const float4*)src)[i];
    v.x = rndf(v.x); v.y = rndf(v.y); v.z = rndf(v.z); v.w = rndf(v.w);
    ((float4*)g_W4[blockIdx.y])[i] = v;
}

// ---------------------------------------------------------------------------
// Projection GEMM core: C[128m x 128n] = A[m,k] * W[n,k]^T + bias
// 3-stage cp.async ring, BK=32, pad-36 rows.
// ---------------------------------------------------------------------------
template<bool GATHER_A, bool SCATTER_OUT>
__device__ __forceinline__ void proj_core(
    const float* __restrict__ Ap, const float* __restrict__ Wp,
    const float* __restrict__ bias, float* __restrict__ outp,
    float oscale, bool oround)
{
    extern __shared__ float smf[];
    float* AsBuf = smf;              // 3 x 4608
    float* BsBuf = smf + 13824;      // 3 x 4608
    const uint32_t As_u = smem_u32(AsBuf);
    const uint32_t Bs_u = smem_u32(BsBuf);

    const int tid  = threadIdx.x;
    const int wid  = tid >> 5;
    const int lane = tid & 31;
    const int g    = lane >> 2;
    const int tg   = lane & 3;
    const int mw   = wid & 3;
    const int nw   = wid >> 2;

    const int m0 = blockIdx.x * 128;
    const int o0 = blockIdx.y * 128;

    const int lr = tid >> 3;          // 0..31
    const int lk = (tid & 7) * 4;     // 0..28

    auto issue = [&](int it, int st) {
        const int k = it * 32 + lk;
        #pragma unroll
        for (int p = 0; p < 4; p++) {
            const int row = lr + p * 32;
            const float* sa;
            if (GATHER_A) {
                int m = m0 + row, bb = m >> 11, n = m & (N_-1);
                int hh = k >> 6, dd = k & 63;
                sa = &g_A[(((size_t)(bb*H_ + hh))*N_ + n)*D_ + dd];
            } else {
                sa = &Ap[(size_t)(m0 + row)*E_ + k];
            }
            cp16(As_u + (uint32_t)(st*18432) + (uint32_t)((row*36 + lk)*4), sa);
            cp16(Bs_u + (uint32_t)(st*18432) + (uint32_t)((row*36 + lk)*4),
                 &Wp[(size_t)(o0 + row)*E_ + k]);
        }
        CP_COMMIT();
    };

    float cacc[2][8][4] = {};

    issue(0, 0);
    issue(1, 1);

    int st = 0;
    for (int it = 0; it < 32; ++it) {
        if (it == 31) CP_WAIT0(); else CP_WAIT1();
        __syncthreads();
        if (it + 2 < 32) {
            int st2 = st + 2; if (st2 >= 3) st2 -= 3;
            issue(it + 2, st2);
        }

        const uint32_t* Au = (const uint32_t*)(AsBuf + st*4608);
        const uint32_t* Bu = (const uint32_t*)(BsBuf + st*4608);
        #pragma unroll
        for (int kb = 0; kb < 4; kb++) {
            uint32_t af[2][4];
            #pragma unroll
            for (int mi = 0; mi < 2; mi++) {
                int r0 = mw*32 + mi*16 + g;
                af[mi][0] = Au[(r0    )*36 + kb*8 + tg    ];
                af[mi][1] = Au[(r0 + 8)*36 + kb*8 + tg    ];
                af[mi][2] = Au[(r0    )*36 + kb*8 + tg + 4];
                af[mi][3] = Au[(r0 + 8)*36 + kb*8 + tg + 4];
            }
            #pragma unroll
            for (int nb = 0; nb < 8; nb++) {
                uint32_t bf[2];
                int c0 = nw*64 + nb*8 + g;
                bf[0] = Bu[c0*36 + kb*8 + tg    ];
                bf[1] = Bu[c0*36 + kb*8 + tg + 4];
                mma8(cacc[0][nb], af[0], bf);
                mma8(cacc[1][nb], af[1], bf);
            }
        }
        if (++st == 3) st = 0;
    }

    // ---- epilogue ----
    #pragma unroll
    for (int mi = 0; mi < 2; mi++) {
        int r0 = m0 + mw*32 + mi*16 + g;
        #pragma unroll
        for (int nb = 0; nb < 8; nb++) {
            int gcol = o0 + nw*64 + nb*8 + 2*tg;
            float b0 = bias[gcol], b1 = bias[gcol + 1];
            float2 v0 = { (cacc[mi][nb][0] + b0)*oscale, (cacc[mi][nb][1] + b1)*oscale };
            float2 v1 = { (cacc[mi][nb][2] + b0)*oscale, (cacc[mi][nb][3] + b1)*oscale };
            if (oround) {
                v0.x = rndf(v0.x); v0.y = rndf(v0.y);
                v1.x = rndf(v1.x); v1.y = rndf(v1.y);
            }
            if (SCATTER_OUT) {
                int hh = gcol >> 6, dd = gcol & 63;
                int bb0 = r0 >> 11, n0 = r0 & (N_-1);
                int r1 = r0 + 8, bb1 = r1 >> 11, n1 = r1 & (N_-1);
                *(float2*)&outp[(((size_t)(bb0*H_ + hh))*N_ + n0)*D_ + dd] = v0;
                *(float2*)&outp[(((size_t)(bb1*H_ + hh))*N_ + n1)*D_ + dd] = v1;
            } else {
                *(float2*)&outp[(size_t)r0*E_ + gcol] = v0;
                *(float2*)&outp[(size_t)(r0 + 8)*E_ + gcol] = v1;
            }
        }
    }
}

__global__ __launch_bounds__(256, 2) void qkv_tc2(
    const float* __restrict__ bq, const float* __restrict__ bk,
    const float* __restrict__ bv)
{
    const float* W; const float* bias; float* out; float sc;
    if (blockIdx.z == 0)      { W = g_W4[0]; bias = bq; out = g_Q; sc = 0.125f; }
    else if (blockIdx.z == 1) { W = g_W4[1]; bias = bk; out = g_K; sc = 1.f; }
    else                      { W = g_W4[2]; bias = bv; out = g_V; sc = 1.f; }
    proj_core<false, true>(g_X, W, bias, out, sc, true);
}

__global__ __launch_bounds__(256, 2) void oproj_tc(
    const float* __restrict__ bo, float* __restrict__ out)
{
    proj_core<true, false>(nullptr, g_W4[3], bo, out, 1.f, false);
}

// ---------------------------------------------------------------------------
// Attention: per (b, h, 128-q tile). 8 warps x 16 q-rows. kv tiles of 64,
// 2-stage cp.async ring. Q pre-scaled+pre-rounded in g_Q; K/V pre-rounded.
// ---------------------------------------------------------------------------
__global__ __launch_bounds__(256, 2) void attn_tc(
    const float* __restrict__ dist,
    const float* __restrict__ dwp, const float* __restrict__ dbp)
{
    extern __shared__ float smf[];
    // stage s: K at s*8704, V at s*8704+4352 ; Ps at 17408 + wid*1088
    const uint32_t sm_u = smem_u32(smf);

    const int tid  = threadIdx.x;
    const int wid  = tid >> 5;
    const int lane = tid & 31;
    const int g    = lane >> 2;
    const int tg   = lane & 3;
    float* Ps = smf + 17408 + wid * 1088;

    const int q0 = blockIdx.x * 128;
    const int h  = blockIdx.y;
    const int b  = blockIdx.z;
    const size_t base = ((size_t)(b*H_ + h)) * N_ * D_;
    const float* Qp = g_Q + base;
    const float* Kp = g_K + base;
    const float* Vp = g_V + base;
    float*       Op = g_A + base;

    const float dw = dwp[0], db = dbp[0];
    const int qr0 = q0 + wid*16 + g;
    const int qr1 = qr0 + 8;

    const int lrow = tid >> 2;         // 0..63
    const int lc   = (tid & 3) * 16;   // float offset

    auto issue_kv = [&](int kt, int stg) {
        const int kv0 = kt * 64;
        const uint32_t kb_u = sm_u + (uint32_t)(stg * 34816);
        #pragma unroll
        for (int j = 0; j < 4; j++) {
            cp16(kb_u          + (uint32_t)((lrow*68 + lc + 4*j)*4),
                 &Kp[(size_t)(kv0 + lrow)*D_ + lc + 4*j]);
            cp16(kb_u + 17408u + (uint32_t)((lrow*68 + lc + 4*j)*4),
                 &Vp[(size_t)(kv0 + lrow)*D_ + lc + 4*j]);
        }
        CP_COMMIT();
    };

    // Q fragments (already tf32-rounded & 0.125-scaled)
    uint32_t qa[8][4];
    #pragma unroll
    for (int kb = 0; kb < 8; kb++) {
        int c = kb*8 + tg;
        qa[kb][0] = __float_as_uint(Qp[(size_t)qr0*D_ + c    ]);
        qa[kb][1] = __float_as_uint(Qp[(size_t)qr1*D_ + c    ]);
        qa[kb][2] = __float_as_uint(Qp[(size_t)qr0*D_ + c + 4]);
        qa[kb][3] = __float_as_uint(Qp[(size_t)qr1*D_ + c + 4]);
    }

    float oc[8][4] = {};
    float mh0 = -INFINITY, mh1 = -INFINITY;
    float lh0 = 0.f, lh1 = 0.f;

    issue_kv(0, 0);

    for (int kt = 0; kt < 32; kt++) {
        const int kv0 = kt * 64;
        const int stg = kt & 1;
        CP_WAIT0();
        __syncthreads();
        if (kt + 1 < 32) issue_kv(kt + 1, stg ^ 1);

        const uint32_t* Ku = (const uint32_t*)(smf + stg*8704);
        const uint32_t* Vu = (const uint32_t*)(smf + stg*8704 + 4352);

        // ---- S = (Q/8) K^T ----
        float sc[8][4] = {};
        #pragma unroll
        for (int kb = 0; kb < 8; kb++) {
            #pragma unroll
            for (int nb = 0; nb < 8; nb++) {
                uint32_t bf[2];
                bf[0] = Ku[(nb*8 + g)*68 + kb*8 + tg    ];
                bf[1] = Ku[(nb*8 + g)*68 + kb*8 + tg + 4];
                mma8(sc[nb], qa[kb], bf);
            }
        }

        // ---- distance bias ----
        #pragma unroll
        for (int nb = 0; nb < 8; nb++) {
            int col = kv0 + nb*8 + 2*tg;
            float2 d0 = *(const float2*)&dist[(size_t)qr0*N_ + col];
            float2 d1 = *(const float2*)&dist[(size_t)qr1*N_ + col];
            sc[nb][0] = fmaf(dw, d0.x, sc[nb][0] + db);
            sc[nb][1] = fmaf(dw, d0.y, sc[nb][1] + db);
            sc[nb][2] = fmaf(dw, d1.x, sc[nb][2] + db);
            sc[nb][3] = fmaf(dw, d1.y, sc[nb][3] + db);
        }

        // ---- online softmax ----
        float mt0 = -INFINITY, mt1 = -INFINITY;
        #pragma unroll
        for (int nb = 0; nb < 8; nb++) {
            mt0 = fmaxf(mt0, fmaxf(sc[nb][0], sc[nb][1]));
            mt1 = fmaxf(mt1, fmaxf(sc[nb][2], sc[nb][3]));
        }
        mt0 = fmaxf(mt0, __shfl_xor_sync(0xffffffffu, mt0, 1));
        mt0 = fmaxf(mt0, __shfl_xor_sync(0xffffffffu, mt0, 2));
        mt1 = fmaxf(mt1, __shfl_xor_sync(0xffffffffu, mt1, 1));
        mt1 = fmaxf(mt1, __shfl_xor_sync(0xffffffffu, mt1, 2));
        float mn0 = fmaxf(mh0, mt0), mn1 = fmaxf(mh1, mt1);
        float corr0 = __expf(mh0 - mn0), corr1 = __expf(mh1 - mn1);
        float s0 = 0.f, s1 = 0.f;
        #pragma unroll
        for (int nb = 0; nb < 8; nb++) {
            sc[nb][0] = __expf(sc[nb][0] - mn0); s0 += sc[nb][0];
            sc[nb][1] = __expf(sc[nb][1] - mn0); s0 += sc[nb][1];
            sc[nb][2] = __expf(sc[nb][2] - mn1); s1 += sc[nb][2];
            sc[nb][3] = __expf(sc[nb][3] - mn1); s1 += sc[nb][3];
        }
        s0 += __shfl_xor_sync(0xffffffffu, s0, 1);
        s0 += __shfl_xor_sync(0xffffffffu, s0, 2);
        s1 += __shfl_xor_sync(0xffffffffu, s1, 1);
        s1 += __shfl_xor_sync(0xffffffffu, s1, 2);
        lh0 = lh0*corr0 + s0;
        lh1 = lh1*corr1 + s1;
        mh0 = mn0; mh1 = mn1;
        #pragma unroll
        for (int nb = 0; nb < 8; nb++) {
            oc[nb][0] *= corr0; oc[nb][1] *= corr0;
            oc[nb][2] *= corr1; oc[nb][3] *= corr1;
        }

        // ---- stage P (tf32) into per-warp smem ----
        #pragma unroll
        for (int nb = 0; nb < 8; nb++) {
            float2 p01 = { rndf(sc[nb][0]), rndf(sc[nb][1]) };
            float2 p23 = { rndf(sc[nb][2]), rndf(sc[nb][3]) };
            *(float2*)&Ps[(g    )*68 + nb*8 + 2*tg] = p01;
            *(float2*)&Ps[(g + 8)*68 + nb*8 + 2*tg] = p23;
        }
        __syncwarp();

        // ---- O += P V ----
        const uint32_t* Pu = (const uint32_t*)Ps;
        #pragma unroll
        for (int kb = 0; kb < 8; kb++) {
            uint32_t af[4];
            af[0] = Pu[(g    )*68 + kb*8 + tg    ];
            af[1] = Pu[(g + 8)*68 + kb*8 + tg    ];
            af[2] = Pu[(g    )*68 + kb*8 + tg + 4];
            af[3] = Pu[(g + 8)*68 + kb*8 + tg + 4];
            #pragma unroll
            for (int nb = 0; nb < 8; nb++) {
                uint32_t bf[2];
                bf[0] = Vu[(kb*8 + tg    )*68 + nb*8 + g];
                bf[1] = Vu[(kb*8 + tg + 4)*68 + nb*8 + g];
                mma8(oc[nb], af, bf);
            }
        }
        __syncwarp();
    }

    const float inv0 = 1.f / lh0, inv1 = 1.f / lh1;
    #pragma unroll
    for (int nb = 0; nb < 8; nb++) {
        int c = nb*8 + 2*tg;
        float2 v0 = { rndf(oc[nb][0]*inv0), rndf(oc[nb][1]*inv0) };
        float2 v1 = { rndf(oc[nb][2]*inv1), rndf(oc[nb][3]*inv1) };
        *(float2*)&Op[(size_t)qr0*D_ + c] = v0;
        *(float2*)&Op[(size_t)qr1*D_ + c] = v1;
    }
}

// ---------------------------------------------------------------------------
extern "C" void kernel_launch(void* const* d_in, const int* in_sizes, int n_in,
                              void* d_out, int out_size)
{
    const float* x    = (const float*)d_in[0];
    const float* dist = (const float*)d_in[1];
    const float* Wq   = (const float*)d_in[2];
    const float* bq   = (const float*)d_in[3];
    const float* Wk   = (const float*)d_in[4];
    const float* bk   = (const float*)d_in[5];
    const float* Wv   = (const float*)d_in[6];
    const float* bv   = (const float*)d_in[7];
    const float* Wo   = (const float*)d_in[8];
    const float* bo   = (const float*)d_in[9];
    const float* dw   = (const float*)d_in[10];
    const float* db   = (const float*)d_in[11];
    float* out = (float*)d_out;

    const int nx4 = M_*E_/4, nw4 = E_*E_/4;
    round_x<<<(nx4 + 255)/256, 256>>>(x, nx4);
    round_w<<<dim3(nw4/256, 4), 256>>>(Wq, Wk, Wv, Wo);

    const int proj_smem = 27648 * (int)sizeof(float);   // 110592 B
    const int attn_smem = 26112 * (int)sizeof(float);   // 104448 B
    cudaFuncSetAttribute(qkv_tc2, cudaFuncAttributeMaxDynamicSharedMemorySize, proj_smem);
    cudaFuncSetAttribute(oproj_tc, cudaFuncAttributeMaxDynamicSharedMemorySize, proj_smem);
    cudaFuncSetAttribute(attn_tc, cudaFuncAttributeMaxDynamicSharedMemorySize, attn_smem);

    qkv_tc2<<<dim3(M_/128, E_/128, 3), 256, proj_smem>>>(bq, bk, bv);
    attn_tc<<<dim3(N_/128, H_, B_), 256, attn_smem>>>(dist, dw, db);
    oproj_tc<<<dim3(M_/128, E_/128), 256, proj_smem>>>(bo, out);
}

// round 8
// speedup vs baseline: 3.3318x; 1.1019x over previous
#include <cuda_runtime.h>
#include <math.h>
#include <stdint.h>

#define B_ 4
#define N_ 2048
#define E_ 1024
#define H_ 16
#define D_ 64
#define M_ (B_*N_)   // 8192

// Scratch.  NOTE: g_V is stored TRANSPOSED per (b,h): [b,h,d,n]
__device__ float g_Q[(size_t)B_*H_*N_*D_];
__device__ float g_K[(size_t)B_*H_*N_*D_];
__device__ float g_V[(size_t)B_*H_*N_*D_];
__device__ float g_A[(size_t)B_*H_*N_*D_];
__device__ float g_X[(size_t)M_*E_];          // pre-rounded x
__device__ float g_W4[4][(size_t)E_*E_];      // pre-rounded Wq,Wk,Wv,Wo

// ---------------------------------------------------------------------------
// helpers
// ---------------------------------------------------------------------------
__device__ __forceinline__ uint32_t f2tf(float x) {
    uint32_t u;
    asm("cvt.rna.tf32.f32 %0, %1;" : "=r"(u) : "f"(x));
    return u;
}
__device__ __forceinline__ float rndf(float x) { return __uint_as_float(f2tf(x)); }

__device__ __forceinline__ void mma8(float* c, const uint32_t* a, const uint32_t* b) {
    asm volatile(
        "mma.sync.aligned.m16n8k8.row.col.f32.tf32.tf32.f32 "
        "{%0,%1,%2,%3}, {%4,%5,%6,%7}, {%8,%9}, {%0,%1,%2,%3};"
        : "+f"(c[0]), "+f"(c[1]), "+f"(c[2]), "+f"(c[3])
        : "r"(a[0]), "r"(a[1]), "r"(a[2]), "r"(a[3]), "r"(b[0]), "r"(b[1]));
}

__device__ __forceinline__ void ldsm4(uint32_t* r, uint32_t addr) {
    asm volatile("ldmatrix.sync.aligned.m8n8.x4.shared.b16 {%0,%1,%2,%3}, [%4];"
                 : "=r"(r[0]), "=r"(r[1]), "=r"(r[2]), "=r"(r[3]) : "r"(addr));
}

__device__ __forceinline__ uint32_t smem_u32(const void* p) {
    uint32_t a;
    asm("{ .reg .u64 t; cvta.to.shared.u64 t, %1; cvt.u32.u64 %0, t; }" : "=r"(a) : "l"(p));
    return a;
}
__device__ __forceinline__ void cp16(uint32_t dst, const void* src) {
    size_t g = __cvta_generic_to_global(src);
    asm volatile("cp.async.cg.shared.global [%0], [%1], 16;" :: "r"(dst), "l"(g));
}
#define CP_COMMIT() asm volatile("cp.async.commit_group;" ::: "memory")
#define CP_WAIT0()  asm volatile("cp.async.wait_group 0;" ::: "memory")
#define CP_WAIT1()  asm volatile("cp.async.wait_group 1;" ::: "memory")

// ---------------------------------------------------------------------------
// Pre-round passes
// ---------------------------------------------------------------------------
__global__ void round_x(const float* __restrict__ src, int n4) {
    int i = blockIdx.x * blockDim.x + threadIdx.x;
    if (i < n4) {
        float4 v = ((const float4*)src)[i];
        v.x = rndf(v.x); v.y = rndf(v.y); v.z = rndf(v.z); v.w = rndf(v.w);
        ((float4*)g_X)[i] = v;
    }
}

__global__ void round_w(const float* __restrict__ wq, const float* __restrict__ wk,
                        const float* __restrict__ wv, const float* __restrict__ wo) {
    const float* src;
    switch (blockIdx.y) {
        case 0: src = wq; break;
        case 1: src = wk; break;
        case 2: src = wv; break;
        default: src = wo; break;
    }
    int i = blockIdx.x * blockDim.x + threadIdx.x;
    float4 v = ((const float4*)src)[i];
    v.x = rndf(v.x); v.y = rndf(v.y); v.z = rndf(v.z); v.w = rndf(v.w);
    ((float4*)g_W4[blockIdx.y])[i] = v;
}

// ---------------------------------------------------------------------------
// Projection GEMM core: C[128m x 128n] = A[m,k] * W[n,k]^T + bias
// 3-stage cp.async ring, BK=32, pad-36 rows, ldmatrix fragment loads.
// out_mode: 0 = linear [m][E]; 1 = scatter [b,h,n,d]; 2 = scatter transposed [b,h,d,n]
// ---------------------------------------------------------------------------
template<bool GATHER_A>
__device__ __forceinline__ void proj_core(
    const float* __restrict__ Ap, const float* __restrict__ Wp,
    const float* __restrict__ bias, float* __restrict__ outp,
    float oscale, bool oround, int out_mode)
{
    extern __shared__ float smf[];
    float* AsBuf = smf;              // 3 x 4608
    float* BsBuf = smf + 13824;      // 3 x 4608
    const uint32_t As_u = smem_u32(AsBuf);
    const uint32_t Bs_u = smem_u32(BsBuf);

    const int tid  = threadIdx.x;
    const int wid  = tid >> 5;
    const int lane = tid & 31;
    const int g    = lane >> 2;
    const int tg   = lane & 3;
    const int mat  = lane >> 3;
    const int mr   = lane & 7;
    const int mw   = wid & 3;
    const int nw   = wid >> 2;

    // per-lane ldmatrix offsets (bytes), row stride 36 floats
    const uint32_t a_loff = (uint32_t)((((mat & 1)*8 + mr)*36 + (mat >> 1)*4) * 4);
    const uint32_t b_loff = (uint32_t)((((mat >> 1)*8 + mr)*36 + (mat & 1)*4) * 4);

    const int m0 = blockIdx.x * 128;
    const int o0 = blockIdx.y * 128;

    const int lr = tid >> 3;          // 0..31
    const int lk = (tid & 7) * 4;     // 0..28

    auto issue = [&](int it, int st) {
        const int k = it * 32 + lk;
        #pragma unroll
        for (int p = 0; p < 4; p++) {
            const int row = lr + p * 32;
            const float* sa;
            if (GATHER_A) {
                int m = m0 + row, bb = m >> 11, n = m & (N_-1);
                int hh = k >> 6, dd = k & 63;
                sa = &g_A[(((size_t)(bb*H_ + hh))*N_ + n)*D_ + dd];
            } else {
                sa = &Ap[(size_t)(m0 + row)*E_ + k];
            }
            cp16(As_u + (uint32_t)(st*18432) + (uint32_t)((row*36 + lk)*4), sa);
            cp16(Bs_u + (uint32_t)(st*18432) + (uint32_t)((row*36 + lk)*4),
                 &Wp[(size_t)(o0 + row)*E_ + k]);
        }
        CP_COMMIT();
    };

    float cacc[2][8][4] = {};

    issue(0, 0);
    issue(1, 1);

    int st = 0;
    for (int it = 0; it < 32; ++it) {
        if (it == 31) CP_WAIT0(); else CP_WAIT1();
        __syncthreads();
        if (it + 2 < 32) {
            int st2 = st + 2; if (st2 >= 3) st2 -= 3;
            issue(it + 2, st2);
        }

        const uint32_t Au_u = As_u + (uint32_t)(st*18432);
        const uint32_t Bu_u = Bs_u + (uint32_t)(st*18432);
        #pragma unroll
        for (int kb = 0; kb < 4; kb++) {
            uint32_t af[2][4];
            ldsm4(af[0], Au_u + (uint32_t)(((mw*32     )*36 + kb*8)*4) + a_loff);
            ldsm4(af[1], Au_u + (uint32_t)(((mw*32 + 16)*36 + kb*8)*4) + a_loff);
            #pragma unroll
            for (int nbp = 0; nbp < 4; nbp++) {
                uint32_t bb[4];
                ldsm4(bb, Bu_u + (uint32_t)(((nw*64 + nbp*16)*36 + kb*8)*4) + b_loff);
                mma8(cacc[0][2*nbp    ], af[0], bb);
                mma8(cacc[0][2*nbp + 1], af[0], bb + 2);
                mma8(cacc[1][2*nbp    ], af[1], bb);
                mma8(cacc[1][2*nbp + 1], af[1], bb + 2);
            }
        }
        if (++st == 3) st = 0;
    }

    // ---- epilogue ----
    #pragma unroll
    for (int mi = 0; mi < 2; mi++) {
        int r0 = m0 + mw*32 + mi*16 + g;
        #pragma unroll
        for (int nb = 0; nb < 8; nb++) {
            int gcol = o0 + nw*64 + nb*8 + 2*tg;
            float b0 = bias[gcol], b1 = bias[gcol + 1];
            float2 v0 = { (cacc[mi][nb][0] + b0)*oscale, (cacc[mi][nb][1] + b1)*oscale };
            float2 v1 = { (cacc[mi][nb][2] + b0)*oscale, (cacc[mi][nb][3] + b1)*oscale };
            if (oround) {
                v0.x = rndf(v0.x); v0.y = rndf(v0.y);
                v1.x = rndf(v1.x); v1.y = rndf(v1.y);
            }
            int r1 = r0 + 8;
            if (out_mode == 1) {
                int hh = gcol >> 6, dd = gcol & 63;
                int bb0 = r0 >> 11, n0 = r0 & (N_-1);
                int bb1 = r1 >> 11, n1 = r1 & (N_-1);
                *(float2*)&outp[(((size_t)(bb0*H_ + hh))*N_ + n0)*D_ + dd] = v0;
                *(float2*)&outp[(((size_t)(bb1*H_ + hh))*N_ + n1)*D_ + dd] = v1;
            } else if (out_mode == 2) {
                int hh = gcol >> 6, dd = gcol & 63;
                int bb0 = r0 >> 11, n0 = r0 & (N_-1);
                int bb1 = r1 >> 11, n1 = r1 & (N_-1);
                float* b0p = &outp[((size_t)(bb0*H_ + hh)*D_ + dd)*N_ + n0];
                float* b1p = &outp[((size_t)(bb1*H_ + hh)*D_ + dd)*N_ + n1];
                b0p[0] = v0.x; b0p[N_] = v0.y;
                b1p[0] = v1.x; b1p[N_] = v1.y;
            } else {
                *(float2*)&outp[(size_t)r0*E_ + gcol] = v0;
                *(float2*)&outp[(size_t)r1*E_ + gcol] = v1;
            }
        }
    }
}

__global__ __launch_bounds__(256, 2) void qkv_tc2(
    const float* __restrict__ bq, const float* __restrict__ bk,
    const float* __restrict__ bv)
{
    const float* W; const float* bias; float* out; float sc; int mode;
    if (blockIdx.z == 0)      { W = g_W4[0]; bias = bq; out = g_Q; sc = 0.125f; mode = 1; }
    else if (blockIdx.z == 1) { W = g_W4[1]; bias = bk; out = g_K; sc = 1.f;    mode = 1; }
    else                      { W = g_W4[2]; bias = bv; out = g_V; sc = 1.f;    mode = 2; }
    proj_core<false>(g_X, W, bias, out, sc, true, mode);
}

__global__ __launch_bounds__(256, 2) void oproj_tc(
    const float* __restrict__ bo, float* __restrict__ out)
{
    proj_core<true>(nullptr, g_W4[3], bo, out, 1.f, false, 0);
}

// ---------------------------------------------------------------------------
// Attention: per (b, h, 256-q tile). 8 warps x 32 q-rows. kv tiles of 64,
// 2-stage cp.async ring, ldmatrix fragment loads, V transposed.
// ---------------------------------------------------------------------------
__global__ __launch_bounds__(256) void attn_tc(
    const float* __restrict__ dist,
    const float* __restrict__ dwp, const float* __restrict__ dbp)
{
    extern __shared__ float smf[];
    // stage s (s=0,1): K at s*8704 floats [kv=64][68], Vt at +4352 [d=64][68]
    // Ps: per warp [32][68] at 17408 + wid*2176
    const uint32_t sm_u = smem_u32(smf);

    const int tid  = threadIdx.x;
    const int wid  = tid >> 5;
    const int lane = tid & 31;
    const int g    = lane >> 2;
    const int tg   = lane & 3;
    const int mat  = lane >> 3;
    const int mr   = lane & 7;

    // per-lane ldmatrix offsets (bytes), row stride 68 floats
    const uint32_t kv_loff = (uint32_t)((((mat >> 1)*8 + mr)*68 + (mat & 1)*4) * 4);
    const uint32_t p_loff  = (uint32_t)((((mat & 1)*8 + mr)*68 + (mat >> 1)*4) * 4);

    float* Ps = smf + 17408 + wid * 2176;
    const uint32_t Ps_u = sm_u + (uint32_t)((17408 + wid*2176) * 4);

    const int q0 = blockIdx.x * 256;
    const int h  = blockIdx.y;
    const int b  = blockIdx.z;
    const size_t base = ((size_t)(b*H_ + h)) * N_ * D_;
    const float* Qp  = g_Q + base;   // [n][d]
    const float* Kp  = g_K + base;   // [n][d]
    const float* Vtp = g_V + base;   // [d][n]  (transposed)
    float*       Op  = g_A + base;   // [n][d]

    const float dw = dwp[0], db = dbp[0];
    const int rbase = q0 + wid * 32;

    const int lrow = tid >> 2;         // 0..63
    const int lc   = (tid & 3) * 16;   // float offset

    auto issue_kv = [&](int kt, int stg) {
        const int kv0 = kt * 64;
        const uint32_t kb_u = sm_u + (uint32_t)(stg * 34816);
        #pragma unroll
        for (int j = 0; j < 4; j++) {
            cp16(kb_u          + (uint32_t)((lrow*68 + lc + 4*j)*4),
                 &Kp[(size_t)(kv0 + lrow)*D_ + lc + 4*j]);
            cp16(kb_u + 17408u + (uint32_t)((lrow*68 + lc + 4*j)*4),
                 &Vtp[(size_t)lrow*N_ + kv0 + lc + 4*j]);
        }
        CP_COMMIT();
    };

    issue_kv(0, 0);

    // Q fragments (already tf32-rounded & 0.125-scaled): 2 M-tiles per warp
    uint32_t qa[8][2][4];
    #pragma unroll
    for (int kb = 0; kb < 8; kb++) {
        int c = kb*8 + tg;
        #pragma unroll
        for (int mi = 0; mi < 2; mi++) {
            int r0 = rbase + mi*16 + g;
            qa[kb][mi][0] = __float_as_uint(Qp[(size_t)r0*D_ + c        ]);
            qa[kb][mi][1] = __float_as_uint(Qp[(size_t)(r0 + 8)*D_ + c  ]);
            qa[kb][mi][2] = __float_as_uint(Qp[(size_t)r0*D_ + c + 4    ]);
            qa[kb][mi][3] = __float_as_uint(Qp[(size_t)(r0 + 8)*D_ + c + 4]);
        }
    }

    float oc[2][8][4] = {};
    float mh[2][2] = {{-INFINITY, -INFINITY}, {-INFINITY, -INFINITY}};
    float lh[2][2] = {{0.f, 0.f}, {0.f, 0.f}};

    for (int kt = 0; kt < 32; kt++) {
        const int kv0 = kt * 64;
        const int stg = kt & 1;
        CP_WAIT0();
        __syncthreads();
        if (kt + 1 < 32) issue_kv(kt + 1, stg ^ 1);

        const uint32_t Ks_u = sm_u + (uint32_t)(stg * 34816);
        const uint32_t Vs_u = Ks_u + 17408u;

        // ---- S = (Q/8) K^T  (both M-tiles) ----
        float sc[2][8][4] = {};
        #pragma unroll
        for (int kb = 0; kb < 8; kb++) {
            #pragma unroll
            for (int nbp = 0; nbp < 4; nbp++) {
                uint32_t bb[4];
                ldsm4(bb, Ks_u + (uint32_t)((nbp*16*68 + kb*8)*4) + kv_loff);
                mma8(sc[0][2*nbp    ], qa[kb][0], bb);
                mma8(sc[0][2*nbp + 1], qa[kb][0], bb + 2);
                mma8(sc[1][2*nbp    ], qa[kb][1], bb);
                mma8(sc[1][2*nbp + 1], qa[kb][1], bb + 2);
            }
        }

        // ---- distance bias ----
        #pragma unroll
        for (int mi = 0; mi < 2; mi++) {
            int r0 = rbase + mi*16 + g;
            #pragma unroll
            for (int nb = 0; nb < 8; nb++) {
                int col = kv0 + nb*8 + 2*tg;
                float2 d0 = *(const float2*)&dist[(size_t)r0*N_ + col];
                float2 d1 = *(const float2*)&dist[(size_t)(r0 + 8)*N_ + col];
                sc[mi][nb][0] = fmaf(dw, d0.x, sc[mi][nb][0] + db);
                sc[mi][nb][1] = fmaf(dw, d0.y, sc[mi][nb][1] + db);
                sc[mi][nb][2] = fmaf(dw, d1.x, sc[mi][nb][2] + db);
                sc[mi][nb][3] = fmaf(dw, d1.y, sc[mi][nb][3] + db);
            }
        }

        // ---- online softmax: 4 row-groups (mi, half) ----
        #pragma unroll
        for (int mi = 0; mi < 2; mi++) {
            float mt0 = -INFINITY, mt1 = -INFINITY;
            #pragma unroll
            for (int nb = 0; nb < 8; nb++) {
                mt0 = fmaxf(mt0, fmaxf(sc[mi][nb][0], sc[mi][nb][1]));
                mt1 = fmaxf(mt1, fmaxf(sc[mi][nb][2], sc[mi][nb][3]));
            }
            mt0 = fmaxf(mt0, __shfl_xor_sync(0xffffffffu, mt0, 1));
            mt0 = fmaxf(mt0, __shfl_xor_sync(0xffffffffu, mt0, 2));
            mt1 = fmaxf(mt1, __shfl_xor_sync(0xffffffffu, mt1, 1));
            mt1 = fmaxf(mt1, __shfl_xor_sync(0xffffffffu, mt1, 2));
            float mn0 = fmaxf(mh[mi][0], mt0), mn1 = fmaxf(mh[mi][1], mt1);
            float corr0 = __expf(mh[mi][0] - mn0), corr1 = __expf(mh[mi][1] - mn1);
            float s0 = 0.f, s1 = 0.f;
            #pragma unroll
            for (int nb = 0; nb < 8; nb++) {
                sc[mi][nb][0] = __expf(sc[mi][nb][0] - mn0); s0 += sc[mi][nb][0];
                sc[mi][nb][1] = __expf(sc[mi][nb][1] - mn0); s0 += sc[mi][nb][1];
                sc[mi][nb][2] = __expf(sc[mi][nb][2] - mn1); s1 += sc[mi][nb][2];
                sc[mi][nb][3] = __expf(sc[mi][nb][3] - mn1); s1 += sc[mi][nb][3];
            }
            s0 += __shfl_xor_sync(0xffffffffu, s0, 1);
            s0 += __shfl_xor_sync(0xffffffffu, s0, 2);
            s1 += __shfl_xor_sync(0xffffffffu, s1, 1);
            s1 += __shfl_xor_sync(0xffffffffu, s1, 2);
            lh[mi][0] = lh[mi][0]*corr0 + s0;
            lh[mi][1] = lh[mi][1]*corr1 + s1;
            mh[mi][0] = mn0; mh[mi][1] = mn1;
            #pragma unroll
            for (int nb = 0; nb < 8; nb++) {
                oc[mi][nb][0] *= corr0; oc[mi][nb][1] *= corr0;
                oc[mi][nb][2] *= corr1; oc[mi][nb][3] *= corr1;
            }
        }

        // ---- stage P (tf32) into per-warp smem [32][68] ----
        #pragma unroll
        for (int mi = 0; mi < 2; mi++) {
            #pragma unroll
            for (int nb = 0; nb < 8; nb++) {
                float2 p01 = { rndf(sc[mi][nb][0]), rndf(sc[mi][nb][1]) };
                float2 p23 = { rndf(sc[mi][nb][2]), rndf(sc[mi][nb][3]) };
                *(float2*)&Ps[(mi*16 + g    )*68 + nb*8 + 2*tg] = p01;
                *(float2*)&Ps[(mi*16 + g + 8)*68 + nb*8 + 2*tg] = p23;
            }
        }
        __syncwarp();

        // ---- O += P V ----
        #pragma unroll
        for (int kb = 0; kb < 8; kb++) {
            uint32_t pa[2][4];
            ldsm4(pa[0], Ps_u + (uint32_t)((kb*8)*4) + p_loff);
            ldsm4(pa[1], Ps_u + (uint32_t)((16*68 + kb*8)*4) + p_loff);
            #pragma unroll
            for (int nbp = 0; nbp < 4; nbp++) {
                uint32_t bb[4];
                ldsm4(bb, Vs_u + (uint32_t)((nbp*16*68 + kb*8)*4) + kv_loff);
                mma8(oc[0][2*nbp    ], pa[0], bb);
                mma8(oc[0][2*nbp + 1], pa[0], bb + 2);
                mma8(oc[1][2*nbp    ], pa[1], bb);
                mma8(oc[1][2*nbp + 1], pa[1], bb + 2);
            }
        }
        __syncwarp();
    }

    // ---- normalize + store (tf32-rounded for oproj's A operand) ----
    #pragma unroll
    for (int mi = 0; mi < 2; mi++) {
        float inv0 = 1.f / lh[mi][0], inv1 = 1.f / lh[mi][1];
        int r0 = rbase + mi*16 + g;
        #pragma unroll
        for (int nb = 0; nb < 8; nb++) {
            int c = nb*8 + 2*tg;
            float2 v0 = { rndf(oc[mi][nb][0]*inv0), rndf(oc[mi][nb][1]*inv0) };
            float2 v1 = { rndf(oc[mi][nb][2]*inv1), rndf(oc[mi][nb][3]*inv1) };
            *(float2*)&Op[(size_t)r0*D_ + c] = v0;
            *(float2*)&Op[(size_t)(r0 + 8)*D_ + c] = v1;
        }
    }
}

// ---------------------------------------------------------------------------
extern "C" void kernel_launch(void* const* d_in, const int* in_sizes, int n_in,
                              void* d_out, int out_size)
{
    const float* x    = (const float*)d_in[0];
    const float* dist = (const float*)d_in[1];
    const float* Wq   = (const float*)d_in[2];
    const float* bq   = (const float*)d_in[3];
    const float* Wk   = (const float*)d_in[4];
    const float* bk   = (const float*)d_in[5];
    const float* Wv   = (const float*)d_in[6];
    const float* bv   = (const float*)d_in[7];
    const float* Wo   = (const float*)d_in[8];
    const float* bo   = (const float*)d_in[9];
    const float* dw   = (const float*)d_in[10];
    const float* db   = (const float*)d_in[11];
    float* out = (float*)d_out;

    const int nx4 = M_*E_/4, nw4 = E_*E_/4;
    round_x<<<(nx4 + 255)/256, 256>>>(x, nx4);
    round_w<<<dim3(nw4/256, 4), 256>>>(Wq, Wk, Wv, Wo);

    const int proj_smem = 27648 * (int)sizeof(float);   // 110592 B
    const int attn_smem = 34816 * (int)sizeof(float);   // 139264 B
    cudaFuncSetAttribute(qkv_tc2, cudaFuncAttributeMaxDynamicSharedMemorySize, proj_smem);
    cudaFuncSetAttribute(oproj_tc, cudaFuncAttributeMaxDynamicSharedMemorySize, proj_smem);
    cudaFuncSetAttribute(attn_tc, cudaFuncAttributeMaxDynamicSharedMemorySize, attn_smem);

    qkv_tc2<<<dim3(M_/128, E_/128, 3), 256, proj_smem>>>(bq, bk, bv);
    attn_tc<<<dim3(N_/256, H_, B_), 256, attn_smem>>>(dist, dw, db);
    oproj_tc<<<dim3(M_/128, E_/128), 256, proj_smem>>>(bo, out);
}

// round 11
// speedup vs baseline: 3.4661x; 1.0403x over previous
#include <cuda_runtime.h>
#include <math.h>
#include <stdint.h>

#define B_ 4
#define N_ 2048
#define E_ 1024
#define H_ 16
#define D_ 64
#define M_ (B_*N_)   // 8192

// Scratch.  NOTE: g_V is stored TRANSPOSED per (b,h): [b,h,d,n]
__device__ float g_Q[(size_t)B_*H_*N_*D_];
__device__ float g_K[(size_t)B_*H_*N_*D_];
__device__ float g_V[(size_t)B_*H_*N_*D_];
__device__ float g_A[(size_t)B_*H_*N_*D_];
__device__ float g_X[(size_t)M_*E_];          // pre-rounded x
__device__ float g_W4[4][(size_t)E_*E_];      // pre-rounded Wq,Wk,Wv,Wo

// ---------------------------------------------------------------------------
// helpers
// ---------------------------------------------------------------------------
__device__ __forceinline__ uint32_t f2tf(float x) {
    uint32_t u;
    asm("cvt.rna.tf32.f32 %0, %1;" : "=r"(u) : "f"(x));
    return u;
}
__device__ __forceinline__ float rndf(float x) { return __uint_as_float(f2tf(x)); }

__device__ __forceinline__ void mma8(float* c, const uint32_t* a, const uint32_t* b) {
    asm volatile(
        "mma.sync.aligned.m16n8k8.row.col.f32.tf32.tf32.f32 "
        "{%0,%1,%2,%3}, {%4,%5,%6,%7}, {%8,%9}, {%0,%1,%2,%3};"
        : "+f"(c[0]), "+f"(c[1]), "+f"(c[2]), "+f"(c[3])
        : "r"(a[0]), "r"(a[1]), "r"(a[2]), "r"(a[3]), "r"(b[0]), "r"(b[1]));
}

__device__ __forceinline__ void ldsm4(uint32_t* r, uint32_t addr) {
    asm volatile("ldmatrix.sync.aligned.m8n8.x4.shared.b16 {%0,%1,%2,%3}, [%4];"
                 : "=r"(r[0]), "=r"(r[1]), "=r"(r[2]), "=r"(r[3]) : "r"(addr));
}

__device__ __forceinline__ uint32_t smem_u32(const void* p) {
    uint32_t a;
    asm("{ .reg .u64 t; cvta.to.shared.u64 t, %1; cvt.u32.u64 %0, t; }" : "=r"(a) : "l"(p));
    return a;
}
__device__ __forceinline__ void cp16(uint32_t dst, const void* src) {
    size_t g = __cvta_generic_to_global(src);
    asm volatile("cp.async.cg.shared.global [%0], [%1], 16;" :: "r"(dst), "l"(g));
}
#define CP_COMMIT() asm volatile("cp.async.commit_group;" ::: "memory")
#define CP_WAIT0()  asm volatile("cp.async.wait_group 0;" ::: "memory")
#define CP_WAIT1()  asm volatile("cp.async.wait_group 1;" ::: "memory")

// ---------------------------------------------------------------------------
// Pre-round passes
// ---------------------------------------------------------------------------
__global__ void round_x(const float* __restrict__ src, int n4) {
    int i = blockIdx.x * blockDim.x + threadIdx.x;
    if (i < n4) {
        float4 v = ((const float4*)src)[i];
        v.x = rndf(v.x); v.y = rndf(v.y); v.z = rndf(v.z); v.w = rndf(v.w);
        ((float4*)g_X)[i] = v;
    }
}

__global__ void round_w(const float* __restrict__ wq, const float* __restrict__ wk,
                        const float* __restrict__ wv, const float* __restrict__ wo) {
    const float* src;
    switch (blockIdx.y) {
        case 0: src = wq; break;
        case 1: src = wk; break;
        case 2: src = wv; break;
        default: src = wo; break;
    }
    int i = blockIdx.x * blockDim.x + threadIdx.x;
    float4 v = ((const float4*)src)[i];
    v.x = rndf(v.x); v.y = rndf(v.y); v.z = rndf(v.z); v.w = rndf(v.w);
    ((float4*)g_W4[blockIdx.y])[i] = v;
}

// ---------------------------------------------------------------------------
// Projection GEMM core: C[128m x 128n] = A[m,k] * W[n,k]^T + bias
// 3-stage cp.async ring, BK=32, pad-36 rows, ldmatrix fragment loads.
// out_mode: 0 = linear [m][E]; 1 = scatter [b,h,n,d]; 2 = scatter transposed [b,h,d,n]
// ---------------------------------------------------------------------------
template<bool GATHER_A>
__device__ __forceinline__ void proj_core(
    const float* __restrict__ Ap, const float* __restrict__ Wp,
    const float* __restrict__ bias, float* __restrict__ outp,
    float oscale, bool oround, int out_mode)
{
    extern __shared__ float smf[];
    float* AsBuf = smf;              // 3 x 4608
    float* BsBuf = smf + 13824;      // 3 x 4608
    const uint32_t As_u = smem_u32(AsBuf);
    const uint32_t Bs_u = smem_u32(BsBuf);

    const int tid  = threadIdx.x;
    const int wid  = tid >> 5;
    const int lane = tid & 31;
    const int g    = lane >> 2;
    const int tg   = lane & 3;
    const int mat  = lane >> 3;
    const int mr   = lane & 7;
    const int mw   = wid & 3;
    const int nw   = wid >> 2;

    // per-lane ldmatrix offsets (bytes), row stride 36 floats
    const uint32_t a_loff = (uint32_t)((((mat & 1)*8 + mr)*36 + (mat >> 1)*4) * 4);
    const uint32_t b_loff = (uint32_t)((((mat >> 1)*8 + mr)*36 + (mat & 1)*4) * 4);

    const int m0 = blockIdx.x * 128;
    const int o0 = blockIdx.y * 128;

    const int lr = tid >> 3;          // 0..31
    const int lk = (tid & 7) * 4;     // 0..28

    auto issue = [&](int it, int st) {
        const int k = it * 32 + lk;
        #pragma unroll
        for (int p = 0; p < 4; p++) {
            const int row = lr + p * 32;
            const float* sa;
            if (GATHER_A) {
                int m = m0 + row, bb = m >> 11, n = m & (N_-1);
                int hh = k >> 6, dd = k & 63;
                sa = &g_A[(((size_t)(bb*H_ + hh))*N_ + n)*D_ + dd];
            } else {
                sa = &Ap[(size_t)(m0 + row)*E_ + k];
            }
            cp16(As_u + (uint32_t)(st*18432) + (uint32_t)((row*36 + lk)*4), sa);
            cp16(Bs_u + (uint32_t)(st*18432) + (uint32_t)((row*36 + lk)*4),
                 &Wp[(size_t)(o0 + row)*E_ + k]);
        }
        CP_COMMIT();
    };

    float cacc[2][8][4] = {};

    issue(0, 0);
    issue(1, 1);

    int st = 0;
    for (int it = 0; it < 32; ++it) {
        if (it == 31) CP_WAIT0(); else CP_WAIT1();
        __syncthreads();
        if (it + 2 < 32) {
            int st2 = st + 2; if (st2 >= 3) st2 -= 3;
            issue(it + 2, st2);
        }

        const uint32_t Au_u = As_u + (uint32_t)(st*18432);
        const uint32_t Bu_u = Bs_u + (uint32_t)(st*18432);
        #pragma unroll
        for (int kb = 0; kb < 4; kb++) {
            uint32_t af[2][4];
            ldsm4(af[0], Au_u + (uint32_t)(((mw*32     )*36 + kb*8)*4) + a_loff);
            ldsm4(af[1], Au_u + (uint32_t)(((mw*32 + 16)*36 + kb*8)*4) + a_loff);
            #pragma unroll
            for (int nbp = 0; nbp < 4; nbp++) {
                uint32_t bb[4];
                ldsm4(bb, Bu_u + (uint32_t)(((nw*64 + nbp*16)*36 + kb*8)*4) + b_loff);
                mma8(cacc[0][2*nbp    ], af[0], bb);
                mma8(cacc[0][2*nbp + 1], af[0], bb + 2);
                mma8(cacc[1][2*nbp    ], af[1], bb);
                mma8(cacc[1][2*nbp + 1], af[1], bb + 2);
            }
        }
        if (++st == 3) st = 0;
    }

    // ---- epilogue ----
    #pragma unroll
    for (int mi = 0; mi < 2; mi++) {
        int r0 = m0 + mw*32 + mi*16 + g;
        #pragma unroll
        for (int nb = 0; nb < 8; nb++) {
            int gcol = o0 + nw*64 + nb*8 + 2*tg;
            float b0 = bias[gcol], b1 = bias[gcol + 1];
            float2 v0 = { (cacc[mi][nb][0] + b0)*oscale, (cacc[mi][nb][1] + b1)*oscale };
            float2 v1 = { (cacc[mi][nb][2] + b0)*oscale, (cacc[mi][nb][3] + b1)*oscale };
            if (oround) {
                v0.x = rndf(v0.x); v0.y = rndf(v0.y);
                v1.x = rndf(v1.x); v1.y = rndf(v1.y);
            }
            int r1 = r0 + 8;
            if (out_mode == 1) {
                int hh = gcol >> 6, dd = gcol & 63;
                int bb0 = r0 >> 11, n0 = r0 & (N_-1);
                int bb1 = r1 >> 11, n1 = r1 & (N_-1);
                *(float2*)&outp[(((size_t)(bb0*H_ + hh))*N_ + n0)*D_ + dd] = v0;
                *(float2*)&outp[(((size_t)(bb1*H_ + hh))*N_ + n1)*D_ + dd] = v1;
            } else if (out_mode == 2) {
                int hh = gcol >> 6, dd = gcol & 63;
                int bb0 = r0 >> 11, n0 = r0 & (N_-1);
                int bb1 = r1 >> 11, n1 = r1 & (N_-1);
                float* b0p = &outp[((size_t)(bb0*H_ + hh)*D_ + dd)*N_ + n0];
                float* b1p = &outp[((size_t)(bb1*H_ + hh)*D_ + dd)*N_ + n1];
                b0p[0] = v0.x; b0p[N_] = v0.y;
                b1p[0] = v1.x; b1p[N_] = v1.y;
            } else {
                *(float2*)&outp[(size_t)r0*E_ + gcol] = v0;
                *(float2*)&outp[(size_t)r1*E_ + gcol] = v1;
            }
        }
    }
}

__global__ void __launch_bounds__(256, 2) qkv_tc2(
    const float* __restrict__ bq, const float* __restrict__ bk,
    const float* __restrict__ bv)
{
    const float* W; const float* bias; float* out; float sc; int mode;
    if (blockIdx.z == 0)      { W = g_W4[0]; bias = bq; out = g_Q; sc = 0.125f; mode = 1; }
    else if (blockIdx.z == 1) { W = g_W4[1]; bias = bk; out = g_K; sc = 1.f;    mode = 1; }
    else                      { W = g_W4[2]; bias = bv; out = g_V; sc = 1.f;    mode = 2; }
    proj_core<false>(g_X, W, bias, out, sc, true, mode);
}

__global__ void __launch_bounds__(256, 2) oproj_tc(
    const float* __restrict__ bo, float* __restrict__ out)
{
    proj_core<true>(nullptr, g_W4[3], bo, out, 1.f, false, 0);
}

// ---------------------------------------------------------------------------
// Attention: per (b, h, 128-q tile). 8 warps x 16 q-rows. kv tiles of 64,
// 2-stage cp.async ring, ldmatrix fragment loads, V transposed.
// launch_bounds(256,2) caps regs at 128 -> 2 CTAs/SM.
// ---------------------------------------------------------------------------
__global__ void __launch_bounds__(256, 2) attn_tc(
    const float* __restrict__ dist,
    const float* __restrict__ dwp, const float* __restrict__ dbp)
{
    extern __shared__ float smf[];
    // stage s (s=0,1): K at s*8704 floats [kv=64][68], Vt at +4352 [d=64][68]
    // Ps: per warp [16][68] at 17408 + wid*1088
    const uint32_t sm_u = smem_u32(smf);

    const int tid  = threadIdx.x;
    const int wid  = tid >> 5;
    const int lane = tid & 31;
    const int g    = lane >> 2;
    const int tg   = lane & 3;
    const int mat  = lane >> 3;
    const int mr   = lane & 7;

    // per-lane ldmatrix offsets (bytes), row stride 68 floats
    const uint32_t kv_loff = (uint32_t)((((mat >> 1)*8 + mr)*68 + (mat & 1)*4) * 4);
    const uint32_t p_loff  = (uint32_t)((((mat & 1)*8 + mr)*68 + (mat >> 1)*4) * 4);

    float* Ps = smf + 17408 + wid * 1088;
    const uint32_t Ps_u = sm_u + (uint32_t)((17408 + wid*1088) * 4);

    const int q0 = blockIdx.x * 128;
    const int h  = blockIdx.y;
    const int b  = blockIdx.z;
    const size_t base = ((size_t)(b*H_ + h)) * N_ * D_;
    const float* Qp  = g_Q + base;   // [n][d]
    const float* Kp  = g_K + base;   // [n][d]
    const float* Vtp = g_V + base;   // [d][n]  (transposed)
    float*       Op  = g_A + base;   // [n][d]

    const float dw = dwp[0], db = dbp[0];
    const int qr0 = q0 + wid*16 + g;
    const int qr1 = qr0 + 8;

    const int lrow = tid >> 2;         // 0..63
    const int lc   = (tid & 3) * 16;   // float offset

    auto issue_kv = [&](int kt, int stg) {
        const int kv0 = kt * 64;
        const uint32_t kb_u = sm_u + (uint32_t)(stg * 34816);
        #pragma unroll
        for (int j = 0; j < 4; j++) {
            cp16(kb_u          + (uint32_t)((lrow*68 + lc + 4*j)*4),
                 &Kp[(size_t)(kv0 + lrow)*D_ + lc + 4*j]);
            cp16(kb_u + 17408u + (uint32_t)((lrow*68 + lc + 4*j)*4),
                 &Vtp[(size_t)lrow*N_ + kv0 + lc + 4*j]);
        }
        CP_COMMIT();
    };

    issue_kv(0, 0);

    // Q fragments (already tf32-rounded & 0.125-scaled)
    uint32_t qa[8][4];
    #pragma unroll
    for (int kb = 0; kb < 8; kb++) {
        int c = kb*8 + tg;
        qa[kb][0] = __float_as_uint(Qp[(size_t)qr0*D_ + c        ]);
        qa[kb][1] = __float_as_uint(Qp[(size_t)qr1*D_ + c        ]);
        qa[kb][2] = __float_as_uint(Qp[(size_t)qr0*D_ + c + 4    ]);
        qa[kb][3] = __float_as_uint(Qp[(size_t)qr1*D_ + c + 4    ]);
    }

    float oc[8][4] = {};
    float mh0 = -INFINITY, mh1 = -INFINITY;
    float lh0 = 0.f, lh1 = 0.f;

    for (int kt = 0; kt < 32; kt++) {
        const int kv0 = kt * 64;
        const int stg = kt & 1;
        CP_WAIT0();
        __syncthreads();
        if (kt + 1 < 32) issue_kv(kt + 1, stg ^ 1);

        const uint32_t Ks_u = sm_u + (uint32_t)(stg * 34816);
        const uint32_t Vs_u = Ks_u + 17408u;

        // ---- S = (Q/8) K^T ----
        float sc[8][4] = {};
        #pragma unroll
        for (int kb = 0; kb < 8; kb++) {
            #pragma unroll
            for (int nbp = 0; nbp < 4; nbp++) {
                uint32_t bb[4];
                ldsm4(bb, Ks_u + (uint32_t)((nbp*16*68 + kb*8)*4) + kv_loff);
                mma8(sc[2*nbp    ], qa[kb], bb);
                mma8(sc[2*nbp + 1], qa[kb], bb + 2);
            }
        }

        // ---- distance bias ----
        #pragma unroll
        for (int nb = 0; nb < 8; nb++) {
            int col = kv0 + nb*8 + 2*tg;
            float2 d0 = *(const float2*)&dist[(size_t)qr0*N_ + col];
            float2 d1 = *(const float2*)&dist[(size_t)qr1*N_ + col];
            sc[nb][0] = fmaf(dw, d0.x, sc[nb][0] + db);
            sc[nb][1] = fmaf(dw, d0.y, sc[nb][1] + db);
            sc[nb][2] = fmaf(dw, d1.x, sc[nb][2] + db);
            sc[nb][3] = fmaf(dw, d1.y, sc[nb][3] + db);
        }

        // ---- online softmax (rows qr0 / qr1, stats shared across lane quad) ----
        float mt0 = -INFINITY, mt1 = -INFINITY;
        #pragma unroll
        for (int nb = 0; nb < 8; nb++) {
            mt0 = fmaxf(mt0, fmaxf(sc[nb][0], sc[nb][1]));
            mt1 = fmaxf(mt1, fmaxf(sc[nb][2], sc[nb][3]));
        }
        mt0 = fmaxf(mt0, __shfl_xor_sync(0xffffffffu, mt0, 1));
        mt0 = fmaxf(mt0, __shfl_xor_sync(0xffffffffu, mt0, 2));
        mt1 = fmaxf(mt1, __shfl_xor_sync(0xffffffffu, mt1, 1));
        mt1 = fmaxf(mt1, __shfl_xor_sync(0xffffffffu, mt1, 2));
        float mn0 = fmaxf(mh0, mt0), mn1 = fmaxf(mh1, mt1);
        float corr0 = __expf(mh0 - mn0), corr1 = __expf(mh1 - mn1);
        float s0 = 0.f, s1 = 0.f;
        #pragma unroll
        for (int nb = 0; nb < 8; nb++) {
            sc[nb][0] = __expf(sc[nb][0] - mn0); s0 += sc[nb][0];
            sc[nb][1] = __expf(sc[nb][1] - mn0); s0 += sc[nb][1];
            sc[nb][2] = __expf(sc[nb][2] - mn1); s1 += sc[nb][2];
            sc[nb][3] = __expf(sc[nb][3] - mn1); s1 += sc[nb][3];
        }
        s0 += __shfl_xor_sync(0xffffffffu, s0, 1);
        s0 += __shfl_xor_sync(0xffffffffu, s0, 2);
        s1 += __shfl_xor_sync(0xffffffffu, s1, 1);
        s1 += __shfl_xor_sync(0xffffffffu, s1, 2);
        lh0 = lh0*corr0 + s0;
        lh1 = lh1*corr1 + s1;
        mh0 = mn0; mh1 = mn1;
        #pragma unroll
        for (int nb = 0; nb < 8; nb++) {
            oc[nb][0] *= corr0; oc[nb][1] *= corr0;
            oc[nb][2] *= corr1; oc[nb][3] *= corr1;
        }

        // ---- stage P (tf32) into per-warp smem [16][68] ----
        #pragma unroll
        for (int nb = 0; nb < 8; nb++) {
            float2 p01 = { rndf(sc[nb][0]), rndf(sc[nb][1]) };
            float2 p23 = { rndf(sc[nb][2]), rndf(sc[nb][3]) };
            *(float2*)&Ps[(g    )*68 + nb*8 + 2*tg] = p01;
            *(float2*)&Ps[(g + 8)*68 + nb*8 + 2*tg] = p23;
        }
        __syncwarp();

        // ---- O += P V ----
        #pragma unroll
        for (int kb = 0; kb < 8; kb++) {
            uint32_t pa[4];
            ldsm4(pa, Ps_u + (uint32_t)((kb*8)*4) + p_loff);
            #pragma unroll
            for (int nbp = 0; nbp < 4; nbp++) {
                uint32_t bb[4];
                ldsm4(bb, Vs_u + (uint32_t)((nbp*16*68 + kb*8)*4) + kv_loff);
                mma8(oc[2*nbp    ], pa, bb);
                mma8(oc[2*nbp + 1], pa, bb + 2);
            }
        }
        __syncwarp();
    }

    // ---- normalize + store (tf32-rounded for oproj's A operand) ----
    const float inv0 = 1.f / lh0, inv1 = 1.f / lh1;
    #pragma unroll
    for (int nb = 0; nb < 8; nb++) {
        int c = nb*8 + 2*tg;
        float2 v0 = { rndf(oc[nb][0]*inv0), rndf(oc[nb][1]*inv0) };
        float2 v1 = { rndf(oc[nb][2]*inv1), rndf(oc[nb][3]*inv1) };
        *(float2*)&Op[(size_t)qr0*D_ + c] = v0;
        *(float2*)&Op[(size_t)(qr1)*D_ + c] = v1;
    }
}

// ---------------------------------------------------------------------------
extern "C" void kernel_launch(void* const* d_in, const int* in_sizes, int n_in,
                              void* d_out, int out_size)
{
    const float* x    = (const float*)d_in[0];
    const float* dist = (const float*)d_in[1];
    const float* Wq   = (const float*)d_in[2];
    const float* bq   = (const float*)d_in[3];
    const float* Wk   = (const float*)d_in[4];
    const float* bk   = (const float*)d_in[5];
    const float* Wv   = (const float*)d_in[6];
    const float* bv   = (const float*)d_in[7];
    const float* Wo   = (const float*)d_in[8];
    const float* bo   = (const float*)d_in[9];
    const float* dw   = (const float*)d_in[10];
    const float* db   = (const float*)d_in[11];
    float* out = (float*)d_out;

    const int nx4 = M_*E_/4, nw4 = E_*E_/4;
    round_x<<<(nx4 + 255)/256, 256>>>(x, nx4);
    round_w<<<dim3(nw4/256, 4), 256>>>(Wq, Wk, Wv, Wo);

    const int proj_smem = 27648 * (int)sizeof(float);   // 110592 B
    const int attn_smem = 26112 * (int)sizeof(float);   // 104448 B
    cudaFuncSetAttribute(qkv_tc2, cudaFuncAttributeMaxDynamicSharedMemorySize, proj_smem);
    cudaFuncSetAttribute(oproj_tc, cudaFuncAttributeMaxDynamicSharedMemorySize, proj_smem);
    cudaFuncSetAttribute(attn_tc, cudaFuncAttributeMaxDynamicSharedMemorySize, attn_smem);

    qkv_tc2<<<dim3(M_/128, E_/128, 3), 256, proj_smem>>>(bq, bk, bv);
    attn_tc<<<dim3(N_/128, H_, B_), 256, attn_smem>>>(dist, dw, db);
    oproj_tc<<<dim3(M_/128, E_/128), 256, proj_smem>>>(bo, out);
}

// round 15
// speedup vs baseline: 3.5733x; 1.0309x over previous
#include <cuda_runtime.h>
#include <math.h>
#include <stdint.h>

#define B_ 4
#define N_ 2048
#define E_ 1024
#define H_ 16
#define D_ 64
#define M_ (B_*N_)   // 8192

// Scratch.  NOTE: g_V is stored TRANSPOSED per (b,h): [b,h,d,n]
__device__ float g_Q[(size_t)B_*H_*N_*D_];
__device__ float g_K[(size_t)B_*H_*N_*D_];
__device__ float g_V[(size_t)B_*H_*N_*D_];
__device__ float g_A[(size_t)B_*H_*N_*D_];
__device__ float g_X[(size_t)M_*E_];          // pre-rounded x
__device__ float g_W4[4][(size_t)E_*E_];      // pre-rounded Wq,Wk,Wv,Wo

// ---------------------------------------------------------------------------
// helpers
// ---------------------------------------------------------------------------
__device__ __forceinline__ uint32_t f2tf(float x) {
    uint32_t u;
    asm("cvt.rna.tf32.f32 %0, %1;" : "=r"(u) : "f"(x));
    return u;
}
__device__ __forceinline__ float rndf(float x) { return __uint_as_float(f2tf(x)); }

__device__ __forceinline__ void mma8(float* c, const uint32_t* a, const uint32_t* b) {
    asm volatile(
        "mma.sync.aligned.m16n8k8.row.col.f32.tf32.tf32.f32 "
        "{%0,%1,%2,%3}, {%4,%5,%6,%7}, {%8,%9}, {%0,%1,%2,%3};"
        : "+f"(c[0]), "+f"(c[1]), "+f"(c[2]), "+f"(c[3])
        : "r"(a[0]), "r"(a[1]), "r"(a[2]), "r"(a[3]), "r"(b[0]), "r"(b[1]));
}

__device__ __forceinline__ void ldsm4(uint32_t* r, uint32_t addr) {
    asm volatile("ldmatrix.sync.aligned.m8n8.x4.shared.b16 {%0,%1,%2,%3}, [%4];"
                 : "=r"(r[0]), "=r"(r[1]), "=r"(r[2]), "=r"(r[3]) : "r"(addr));
}

__device__ __forceinline__ uint32_t smem_u32(const void* p) {
    uint32_t a;
    asm("{ .reg .u64 t; cvta.to.shared.u64 t, %1; cvt.u32.u64 %0, t; }" : "=r"(a) : "l"(p));
    return a;
}
__device__ __forceinline__ void cp16(uint32_t dst, const void* src) {
    size_t g = __cvta_generic_to_global(src);
    asm volatile("cp.async.cg.shared.global [%0], [%1], 16;" :: "r"(dst), "l"(g));
}
#define CP_COMMIT() asm volatile("cp.async.commit_group;" ::: "memory")
#define CP_WAIT0()  asm volatile("cp.async.wait_group 0;" ::: "memory")
#define CP_WAIT1()  asm volatile("cp.async.wait_group 1;" ::: "memory")

// ---------------------------------------------------------------------------
// Pre-round passes
// ---------------------------------------------------------------------------
__global__ void round_x(const float* __restrict__ src, int n4) {
    int i = blockIdx.x * blockDim.x + threadIdx.x;
    if (i < n4) {
        float4 v = ((const float4*)src)[i];
        v.x = rndf(v.x); v.y = rndf(v.y); v.z = rndf(v.z); v.w = rndf(v.w);
        ((float4*)g_X)[i] = v;
    }
}

__global__ void round_w(const float* __restrict__ wq, const float* __restrict__ wk,
                        const float* __restrict__ wv, const float* __restrict__ wo) {
    const float* src;
    switch (blockIdx.y) {
        case 0: src = wq; break;
        case 1: src = wk; break;
        case 2: src = wv; break;
        default: src = wo; break;
    }
    int i = blockIdx.x * blockDim.x + threadIdx.x;
    float4 v = ((const float4*)src)[i];
    v.x = rndf(v.x); v.y = rndf(v.y); v.z = rndf(v.z); v.w = rndf(v.w);
    ((float4*)g_W4[blockIdx.y])[i] = v;
}

// ---------------------------------------------------------------------------
// Projection GEMM core: C[128m x 128n] = A[m,k] * W[n,k]^T + bias
// 3-stage cp.async ring, BK=32, pad-36 rows, ldmatrix fragment loads.
// out_mode: 0 = linear [m][E]; 1 = scatter [b,h,n,d]; 2 = scatter transposed [b,h,d,n]
// ---------------------------------------------------------------------------
template<bool GATHER_A>
__device__ __forceinline__ void proj_core(
    const float* __restrict__ Ap, const float* __restrict__ Wp,
    const float* __restrict__ bias, float* __restrict__ outp,
    float oscale, bool oround, int out_mode)
{
    extern __shared__ float smf[];
    float* AsBuf = smf;              // 3 x 4608
    float* BsBuf = smf + 13824;      // 3 x 4608
    const uint32_t As_u = smem_u32(AsBuf);
    const uint32_t Bs_u = smem_u32(BsBuf);

    const int tid  = threadIdx.x;
    const int wid  = tid >> 5;
    const int lane = tid & 31;
    const int g    = lane >> 2;
    const int tg   = lane & 3;
    const int mat  = lane >> 3;
    const int mr   = lane & 7;
    const int mw   = wid & 3;
    const int nw   = wid >> 2;

    // per-lane ldmatrix offsets (bytes), row stride 36 floats
    const uint32_t a_loff = (uint32_t)((((mat & 1)*8 + mr)*36 + (mat >> 1)*4) * 4);
    const uint32_t b_loff = (uint32_t)((((mat >> 1)*8 + mr)*36 + (mat & 1)*4) * 4);

    const int m0 = blockIdx.x * 128;
    const int o0 = blockIdx.y * 128;

    const int lr = tid >> 3;          // 0..31
    const int lk = (tid & 7) * 4;     // 0..28

    auto issue = [&](int it, int st) {
        const int k = it * 32 + lk;
        #pragma unroll
        for (int p = 0; p < 4; p++) {
            const int row = lr + p * 32;
            const float* sa;
            if (GATHER_A) {
                int m = m0 + row, bb = m >> 11, n = m & (N_-1);
                int hh = k >> 6, dd = k & 63;
                sa = &g_A[(((size_t)(bb*H_ + hh))*N_ + n)*D_ + dd];
            } else {
                sa = &Ap[(size_t)(m0 + row)*E_ + k];
            }
            cp16(As_u + (uint32_t)(st*18432) + (uint32_t)((row*36 + lk)*4), sa);
            cp16(Bs_u + (uint32_t)(st*18432) + (uint32_t)((row*36 + lk)*4),
                 &Wp[(size_t)(o0 + row)*E_ + k]);
        }
        CP_COMMIT();
    };

    float cacc[2][8][4] = {};

    issue(0, 0);
    issue(1, 1);

    int st = 0;
    for (int it = 0; it < 32; ++it) {
        if (it == 31) CP_WAIT0(); else CP_WAIT1();
        __syncthreads();
        if (it + 2 < 32) {
            int st2 = st + 2; if (st2 >= 3) st2 -= 3;
            issue(it + 2, st2);
        }

        const uint32_t Au_u = As_u + (uint32_t)(st*18432);
        const uint32_t Bu_u = Bs_u + (uint32_t)(st*18432);
        #pragma unroll
        for (int kb = 0; kb < 4; kb++) {
            uint32_t af[2][4];
            ldsm4(af[0], Au_u + (uint32_t)(((mw*32     )*36 + kb*8)*4) + a_loff);
            ldsm4(af[1], Au_u + (uint32_t)(((mw*32 + 16)*36 + kb*8)*4) + a_loff);
            #pragma unroll
            for (int nbp = 0; nbp < 4; nbp++) {
                uint32_t bb[4];
                ldsm4(bb, Bu_u + (uint32_t)(((nw*64 + nbp*16)*36 + kb*8)*4) + b_loff);
                mma8(cacc[0][2*nbp    ], af[0], bb);
                mma8(cacc[0][2*nbp + 1], af[0], bb + 2);
                mma8(cacc[1][2*nbp    ], af[1], bb);
                mma8(cacc[1][2*nbp + 1], af[1], bb + 2);
            }
        }
        if (++st == 3) st = 0;
    }

    // ---- epilogue ----
    #pragma unroll
    for (int mi = 0; mi < 2; mi++) {
        int r0 = m0 + mw*32 + mi*16 + g;
        #pragma unroll
        for (int nb = 0; nb < 8; nb++) {
            int gcol = o0 + nw*64 + nb*8 + 2*tg;
            float b0 = bias[gcol], b1 = bias[gcol + 1];
            float2 v0 = { (cacc[mi][nb][0] + b0)*oscale, (cacc[mi][nb][1] + b1)*oscale };
            float2 v1 = { (cacc[mi][nb][2] + b0)*oscale, (cacc[mi][nb][3] + b1)*oscale };
            if (oround) {
                v0.x = rndf(v0.x); v0.y = rndf(v0.y);
                v1.x = rndf(v1.x); v1.y = rndf(v1.y);
            }
            int r1 = r0 + 8;
            if (out_mode == 1) {
                int hh = gcol >> 6, dd = gcol & 63;
                int bb0 = r0 >> 11, n0 = r0 & (N_-1);
                int bb1 = r1 >> 11, n1 = r1 & (N_-1);
                *(float2*)&outp[(((size_t)(bb0*H_ + hh))*N_ + n0)*D_ + dd] = v0;
                *(float2*)&outp[(((size_t)(bb1*H_ + hh))*N_ + n1)*D_ + dd] = v1;
            } else if (out_mode == 2) {
                int hh = gcol >> 6, dd = gcol & 63;
                int bb0 = r0 >> 11, n0 = r0 & (N_-1);
                int bb1 = r1 >> 11, n1 = r1 & (N_-1);
                float* b0p = &outp[((size_t)(bb0*H_ + hh)*D_ + dd)*N_ + n0];
                float* b1p = &outp[((size_t)(bb1*H_ + hh)*D_ + dd)*N_ + n1];
                b0p[0] = v0.x; b0p[N_] = v0.y;
                b1p[0] = v1.x; b1p[N_] = v1.y;
            } else {
                *(float2*)&outp[(size_t)r0*E_ + gcol] = v0;
                *(float2*)&outp[(size_t)r1*E_ + gcol] = v1;
            }
        }
    }
}

__global__ void __launch_bounds__(256, 2) qkv_tc2(
    const float* __restrict__ bq, const float* __restrict__ bk,
    const float* __restrict__ bv)
{
    const float* W; const float* bias; float* out; float sc; int mode;
    if (blockIdx.z == 0)      { W = g_W4[0]; bias = bq; out = g_Q; sc = 0.125f; mode = 1; }
    else if (blockIdx.z == 1) { W = g_W4[1]; bias = bk; out = g_K; sc = 1.f;    mode = 1; }
    else                      { W = g_W4[2]; bias = bv; out = g_V; sc = 1.f;    mode = 2; }
    proj_core<false>(g_X, W, bias, out, sc, true, mode);
}

__global__ void __launch_bounds__(256, 2) oproj_tc(
    const float* __restrict__ bo, float* __restrict__ out)
{
    proj_core<true>(nullptr, g_W4[3], bo, out, 1.f, false, 0);
}

// ---------------------------------------------------------------------------
// Attention: per (b, h, 128-q tile). 8 warps x 16 q-rows. kv tiles of 64,
// 2-stage cp.async ring, ldmatrix K/V fragments, V transposed.
// P re-fragmented via register shuffles (no smem round-trip).
// ---------------------------------------------------------------------------
__global__ void __launch_bounds__(256, 2) attn_tc(
    const float* __restrict__ dist,
    const float* __restrict__ dwp, const float* __restrict__ dbp)
{
    extern __shared__ float smf[];
    // stage s (s=0,1): K at s*8704 floats [kv=64][68], Vt at +4352 [d=64][68]
    const uint32_t sm_u = smem_u32(smf);

    const int tid  = threadIdx.x;
    const int wid  = tid >> 5;
    const int lane = tid & 31;
    const int g    = lane >> 2;
    const int tg   = lane & 3;
    const int mat  = lane >> 3;
    const int mr   = lane & 7;

    // per-lane ldmatrix offset (bytes), row stride 68 floats (B-fragments)
    const uint32_t kv_loff = (uint32_t)((((mat >> 1)*8 + mr)*68 + (mat & 1)*4) * 4);

    // shfl sources for P re-fragmentation
    const int srcA = g*4 + (tg >> 1);
    const int srcB = srcA + 2;
    const bool podd = (tg & 1);

    const int q0 = blockIdx.x * 128;
    const int h  = blockIdx.y;
    const int b  = blockIdx.z;
    const size_t base = ((size_t)(b*H_ + h)) * N_ * D_;
    const float* Qp  = g_Q + base;   // [n][d]
    const float* Kp  = g_K + base;   // [n][d]
    const float* Vtp = g_V + base;   // [d][n]  (transposed)
    float*       Op  = g_A + base;   // [n][d]

    const float dw = dwp[0], db = dbp[0];
    const int qr0 = q0 + wid*16 + g;
    const int qr1 = qr0 + 8;

    const int lrow = tid >> 2;         // 0..63
    const int lc   = (tid & 3) * 16;   // float offset

    auto issue_kv = [&](int kt, int stg) {
        const int kv0 = kt * 64;
        const uint32_t kb_u = sm_u + (uint32_t)(stg * 34816);
        #pragma unroll
        for (int j = 0; j < 4; j++) {
            cp16(kb_u          + (uint32_t)((lrow*68 + lc + 4*j)*4),
                 &Kp[(size_t)(kv0 + lrow)*D_ + lc + 4*j]);
            cp16(kb_u + 17408u + (uint32_t)((lrow*68 + lc + 4*j)*4),
                 &Vtp[(size_t)lrow*N_ + kv0 + lc + 4*j]);
        }
        CP_COMMIT();
    };

    issue_kv(0, 0);

    // Q fragments (already tf32-rounded & 0.125-scaled)
    uint32_t qa[8][4];
    #pragma unroll
    for (int kb = 0; kb < 8; kb++) {
        int c = kb*8 + tg;
        qa[kb][0] = __float_as_uint(Qp[(size_t)qr0*D_ + c        ]);
        qa[kb][1] = __float_as_uint(Qp[(size_t)qr1*D_ + c        ]);
        qa[kb][2] = __float_as_uint(Qp[(size_t)qr0*D_ + c + 4    ]);
        qa[kb][3] = __float_as_uint(Qp[(size_t)qr1*D_ + c + 4    ]);
    }

    float oc[8][4] = {};
    float mh0 = -INFINITY, mh1 = -INFINITY;
    float lh0 = 0.f, lh1 = 0.f;

    for (int kt = 0; kt < 32; kt++) {
        const int kv0 = kt * 64;
        const int stg = kt & 1;
        CP_WAIT0();
        __syncthreads();
        if (kt + 1 < 32) issue_kv(kt + 1, stg ^ 1);

        const uint32_t Ks_u = sm_u + (uint32_t)(stg * 34816);
        const uint32_t Vs_u = Ks_u + 17408u;

        // ---- S = (Q/8) K^T ----
        float sc[8][4] = {};
        #pragma unroll
        for (int kb = 0; kb < 8; kb++) {
            #pragma unroll
            for (int nbp = 0; nbp < 4; nbp++) {
                uint32_t bb[4];
                ldsm4(bb, Ks_u + (uint32_t)((nbp*16*68 + kb*8)*4) + kv_loff);
                mma8(sc[2*nbp    ], qa[kb], bb);
                mma8(sc[2*nbp + 1], qa[kb], bb + 2);
            }
        }

        // ---- distance bias ----
        #pragma unroll
        for (int nb = 0; nb < 8; nb++) {
            int col = kv0 + nb*8 + 2*tg;
            float2 d0 = *(const float2*)&dist[(size_t)qr0*N_ + col];
            float2 d1 = *(const float2*)&dist[(size_t)qr1*N_ + col];
            sc[nb][0] = fmaf(dw, d0.x, sc[nb][0] + db);
            sc[nb][1] = fmaf(dw, d0.y, sc[nb][1] + db);
            sc[nb][2] = fmaf(dw, d1.x, sc[nb][2] + db);
            sc[nb][3] = fmaf(dw, d1.y, sc[nb][3] + db);
        }

        // ---- online softmax (rows qr0 / qr1, stats shared across lane quad) ----
        float mt0 = -INFINITY, mt1 = -INFINITY;
        #pragma unroll
        for (int nb = 0; nb < 8; nb++) {
            mt0 = fmaxf(mt0, fmaxf(sc[nb][0], sc[nb][1]));
            mt1 = fmaxf(mt1, fmaxf(sc[nb][2], sc[nb][3]));
        }
        mt0 = fmaxf(mt0, __shfl_xor_sync(0xffffffffu, mt0, 1));
        mt0 = fmaxf(mt0, __shfl_xor_sync(0xffffffffu, mt0, 2));
        mt1 = fmaxf(mt1, __shfl_xor_sync(0xffffffffu, mt1, 1));
        mt1 = fmaxf(mt1, __shfl_xor_sync(0xffffffffu, mt1, 2));
        float mn0 = fmaxf(mh0, mt0), mn1 = fmaxf(mh1, mt1);
        float corr0 = __expf(mh0 - mn0), corr1 = __expf(mh1 - mn1);
        float s0 = 0.f, s1 = 0.f;
        #pragma unroll
        for (int nb = 0; nb < 8; nb++) {
            sc[nb][0] = __expf(sc[nb][0] - mn0); s0 += sc[nb][0];
            sc[nb][1] = __expf(sc[nb][1] - mn0); s0 += sc[nb][1];
            sc[nb][2] = __expf(sc[nb][2] - mn1); s1 += sc[nb][2];
            sc[nb][3] = __expf(sc[nb][3] - mn1); s1 += sc[nb][3];
        }
        s0 += __shfl_xor_sync(0xffffffffu, s0, 1);
        s0 += __shfl_xor_sync(0xffffffffu, s0, 2);
        s1 += __shfl_xor_sync(0xffffffffu, s1, 1);
        s1 += __shfl_xor_sync(0xffffffffu, s1, 2);
        lh0 = lh0*corr0 + s0;
        lh1 = lh1*corr1 + s1;
        mh0 = mn0; mh1 = mn1;
        #pragma unroll
        for (int nb = 0; nb < 8; nb++) {
            oc[nb][0] *= corr0; oc[nb][1] *= corr0;
            oc[nb][2] *= corr1; oc[nb][3] *= corr1;
        }

        // ---- round P to tf32 in place (C-fragment layout) ----
        uint32_t pu[8][4];
        #pragma unroll
        for (int nb = 0; nb < 8; nb++) {
            pu[nb][0] = f2tf(sc[nb][0]);
            pu[nb][1] = f2tf(sc[nb][1]);
            pu[nb][2] = f2tf(sc[nb][2]);
            pu[nb][3] = f2tf(sc[nb][3]);
        }

        // ---- O += P V : re-fragment P via shuffles, V via ldmatrix ----
        #pragma unroll
        for (int kb = 0; kb < 8; kb++) {
            uint32_t p0 = __shfl_sync(0xffffffffu, pu[kb][0], srcA);
            uint32_t p1 = __shfl_sync(0xffffffffu, pu[kb][1], srcA);
            uint32_t p2 = __shfl_sync(0xffffffffu, pu[kb][2], srcA);
            uint32_t p3 = __shfl_sync(0xffffffffu, pu[kb][3], srcA);
            uint32_t r0 = __shfl_sync(0xffffffffu, pu[kb][0], srcB);
            uint32_t r1 = __shfl_sync(0xffffffffu, pu[kb][1], srcB);
            uint32_t r2 = __shfl_sync(0xffffffffu, pu[kb][2], srcB);
            uint32_t r3 = __shfl_sync(0xffffffffu, pu[kb][3], srcB);
            uint32_t pa[4];
            pa[0] = podd ? p1 : p0;   // P[qr0][kb*8+tg]
            pa[1] = podd ? p3 : p2;   // P[qr1][kb*8+tg]
            pa[2] = podd ? r1 : r0;   // P[qr0][kb*8+tg+4]
            pa[3] = podd ? r3 : r2;   // P[qr1][kb*8+tg+4]
            #pragma unroll
            for (int nbp = 0; nbp < 4; nbp++) {
                uint32_t bb[4];
                ldsm4(bb, Vs_u + (uint32_t)((nbp*16*68 + kb*8)*4) + kv_loff);
                mma8(oc[2*nbp    ], pa, bb);
                mma8(oc[2*nbp + 1], pa, bb + 2);
            }
        }
    }

    // ---- normalize + store (tf32-rounded for oproj's A operand) ----
    const float inv0 = 1.f / lh0, inv1 = 1.f / lh1;
    #pragma unroll
    for (int nb = 0; nb < 8; nb++) {
        int c = nb*8 + 2*tg;
        float2 v0 = { rndf(oc[nb][0]*inv0), rndf(oc[nb][1]*inv0) };
        float2 v1 = { rndf(oc[nb][2]*inv1), rndf(oc[nb][3]*inv1) };
        *(float2*)&Op[(size_t)qr0*D_ + c] = v0;
        *(float2*)&Op[(size_t)qr1*D_ + c] = v1;
    }
}

// ---------------------------------------------------------------------------
extern "C" void kernel_launch(void* const* d_in, const int* in_sizes, int n_in,
                              void* d_out, int out_size)
{
    const float* x    = (const float*)d_in[0];
    const float* dist = (const float*)d_in[1];
    const float* Wq   = (const float*)d_in[2];
    const float* bq   = (const float*)d_in[3];
    const float* Wk   = (const float*)d_in[4];
    const float* bk   = (const float*)d_in[5];
    const float* Wv   = (const float*)d_in[6];
    const float* bv   = (const float*)d_in[7];
    const float* Wo   = (const float*)d_in[8];
    const float* bo   = (const float*)d_in[9];
    const float* dw   = (const float*)d_in[10];
    const float* db   = (const float*)d_in[11];
    float* out = (float*)d_out;

    const int nx4 = M_*E_/4, nw4 = E_*E_/4;
    round_x<<<(nx4 + 255)/256, 256>>>(x, nx4);
    round_w<<<dim3(nw4/256, 4), 256>>>(Wq, Wk, Wv, Wo);

    const int proj_smem = 27648 * (int)sizeof(float);   // 110592 B
    const int attn_smem = 17408 * (int)sizeof(float);   // 69632 B
    cudaFuncSetAttribute(qkv_tc2, cudaFuncAttributeMaxDynamicSharedMemorySize, proj_smem);
    cudaFuncSetAttribute(oproj_tc, cudaFuncAttributeMaxDynamicSharedMemorySize, proj_smem);
    cudaFuncSetAttribute(attn_tc, cudaFuncAttributeMaxDynamicSharedMemorySize, attn_smem);

    qkv_tc2<<<dim3(M_/128, E_/128, 3), 256, proj_smem>>>(bq, bk, bv);
    attn_tc<<<dim3(N_/128, H_, B_), 256, attn_smem>>>(dist, dw, db);
    oproj_tc<<<dim3(M_/128, E_/128), 256, proj_smem>>>(bo, out);
}